// round 14
// baseline (speedup 1.0000x reference)
#include <cuda_runtime.h>
#include <cuda_fp16.h>
#include <math.h>
#include <stdint.h>

// ---------------------------------------------------------------------------
// Problem constants
// ---------------------------------------------------------------------------
#define Bsz   2
#define Ntok  2048
#define Dm    1024
#define Hh    16
#define DHd   64
#define Ii    1024
#define DCc   768
#define Mctx  77
#define MctxP 80
#define FFd   4096
#define BN    (Bsz*Ntok)
#define BM2   (Bsz*Mctx)
#define BHh   (Bsz*Hh)
#define SCALE 0.125f

// ---------------------------------------------------------------------------
// Device scratch
// ---------------------------------------------------------------------------
#define DEVARR(name, type, count) __device__ __align__(16) type name[(size_t)(count)]

DEVARR(g_lnh,  half, BN*Dm);
DEVARR(g_qh,   half, BN*Ii);
DEVARR(g_kh,   half, BN*Ii);
DEVARR(g_vh,   half, BN*Ii);            // self V, fp16 [tok][1024]
DEVARR(g_v,    float, BM2*Ii);          // cross V fp32
DEVARR(g_vth,  half, BHh*DHd*MctxP);    // cross V transposed
DEVARR(g_sim,  float, (size_t)BHh*Ntok*MctxP);
DEVARR(g_Ph,   half, (size_t)BHh*Ntok*MctxP); DEVARR(g_Pl, half, (size_t)BHh*Ntok*MctxP);
DEVARR(g_atth, half, BN*Ii);
DEVARR(g_x1,   float, BN*Dm);  DEVARR(g_x2,   float, BN*Dm);
DEVARR(g_ctxh, half, BM2*DCc);
DEVARR(g_ffh,  half, (size_t)BN*FFd);
// transposed weights [N x K], hi only
DEVARR(g_wqkv1, half, (size_t)3*Dm*Ii);
DEVARR(g_wo1h,  half, Dm*Ii);
DEVARR(g_wq2h,  half, Dm*Ii);
DEVARR(g_wkv2,  half, (size_t)2*Ii*DCc);
DEVARR(g_wo2h,  half, Dm*Ii);
DEVARR(g_wf1h,  half, (size_t)Dm*2*FFd);   // interleaved: row 2j=h, 2j+1=gate
DEVARR(g_wf2h,  half, (size_t)FFd*Dm);

// ---------------------------------------------------------------------------
// Helpers
// ---------------------------------------------------------------------------
__device__ __forceinline__ uint32_t smem_u32(const void* p) {
    uint32_t a;
    asm("{ .reg .u64 t; cvta.to.shared.u64 t, %1; cvt.u32.u64 %0, t; }" : "=r"(a) : "l"(p));
    return a;
}
__device__ __forceinline__ void split2(float x, half& h, half& l) {
    h = __float2half_rn(x);
    l = __float2half_rn(x - __half2float(h));
}
__device__ __forceinline__ float gelu_exact(float g) {
    return 0.5f * g * (1.f + erff(g * 0.70710678118654752440f));
}

#define LDSM4(r0, r1, r2, r3, addr) \
    asm volatile("ldmatrix.sync.aligned.m8n8.x4.shared.b16 {%0,%1,%2,%3}, [%4];" \
        : "=r"(r0), "=r"(r1), "=r"(r2), "=r"(r3) : "r"(addr))

#define LDSM4T(r0, r1, r2, r3, addr) \
    asm volatile("ldmatrix.sync.aligned.m8n8.x4.trans.shared.b16 {%0,%1,%2,%3}, [%4];" \
        : "=r"(r0), "=r"(r1), "=r"(r2), "=r"(r3) : "r"(addr))

#define MMA16816(c, a, b0, b1) \
    asm volatile("mma.sync.aligned.m16n8k16.row.col.f32.f16.f16.f32 " \
        "{%0,%1,%2,%3}, {%4,%5,%6,%7}, {%8,%9}, {%0,%1,%2,%3};" \
        : "+f"((c)[0]), "+f"((c)[1]), "+f"((c)[2]), "+f"((c)[3]) \
        : "r"((a)[0]), "r"((a)[1]), "r"((a)[2]), "r"((a)[3]), "r"(b0), "r"(b1))

#define CP_ASYNC16(dst, src) \
    asm volatile("cp.async.cg.shared.global [%0], [%1], 16;" :: "r"(dst), "l"(src) : "memory")
#define CP_COMMIT() asm volatile("cp.async.commit_group;" ::: "memory")

// ---------------------------------------------------------------------------
// mma.sync GEMM: acc = A @ Bh^T, 128x128 tile, 8 warps.
// 3-buffer rotation, depth-1 prefetch, ONE __syncthreads per stage.
// MODE 0: C/Ch = alpha*acc (+bias)(+resid); 1: GEGLU; 2: QKV route; 3: KV route
// ---------------------------------------------------------------------------
template<int SPLIT_A, int MODE, int BK>
__global__ void __launch_bounds__(256, 2) mma_gemm(
    const half* __restrict__ Ah_, const half* __restrict__ Al_,
    const half* __restrict__ Bh_,
    const float* __restrict__ bias, const float* __restrict__ resid,
    float* __restrict__ C, half* __restrict__ Ch, half* __restrict__ Ch2,
    int M, int N, int K, int lda, int ldb, int ldc,
    long long aO, long long aI, long long bO, long long bI,
    long long cO, long long cI, int nInner, float alpha)
{
    constexpr int NT  = 2 + SPLIT_A;
    constexpr int PK  = BK + 8;
    constexpr int TH  = 128 * PK;
    constexpr int SPT = 128 * (BK / 8);
    constexpr int ITR = NT * SPT / 256;

    extern __shared__ half sm[];
    uint32_t smBase = smem_u32(sm);
    int tid = threadIdx.x, lane = tid & 31, wid = tid >> 5;
    int warpM = wid >> 1, warpN = wid & 1;

    int z = blockIdx.z, zo = z / nInner, zi = z % nInner;
    const half* Ahp = Ah_ + (long long)zo * aO + (long long)zi * aI;
    const half* Alp = SPLIT_A ? (Al_ + (long long)zo * aO + (long long)zi * aI) : nullptr;
    const half* Bhp = Bh_ + (long long)zo * bO + (long long)zi * bI;
    long long offC = (long long)zo * cO + (long long)zi * cI;

    int rowBase = blockIdx.y * 128, colBase = blockIdx.x * 128;

    float acc[2][8][4];
    #pragma unroll
    for (int i = 0; i < 2; i++)
        #pragma unroll
        for (int j = 0; j < 8; j++)
            #pragma unroll
            for (int e = 0; e < 4; e++) acc[i][j][e] = 0.f;

    int nc = (K + BK - 1) / BK;

    auto load_stage = [&](int c, int s) {
        int k0 = c * BK;
        #pragma unroll
        for (int i = 0; i < ITR; i++) {
            int seg  = tid + (i << 8);
            int tile = seg / SPT;
            int w    = seg % SPT;
            int row  = w / (BK / 8);
            int cs   = (w % (BK / 8)) << 3;
            bool isA = tile < (NT - 1);
            const half* base = (tile == 0) ? Ahp : (SPLIT_A && tile == 1) ? Alp : Bhp;
            int ld  = isA ? lda : ldb;
            int gr  = (isA ? rowBase : colBase) + row;
            int gk  = k0 + cs;
            bool ok = (gr < (isA ? M : N)) && (gk + 8 <= K);
            const half* src = ok ? (base + (size_t)gr * ld + gk) : base;
            uint32_t dst = smBase + (uint32_t)(((s * NT + tile) * TH + row * PK + cs) * 2);
            uint32_t sz = ok ? 16u : 0u;
            asm volatile("cp.async.cg.shared.global [%0], [%1], 16, %2;"
                         :: "r"(dst), "l"(src), "r"(sz) : "memory");
        }
    };

    int aRow = (lane & 7) + ((lane >> 3) & 1) * 8;
    int aCg  = (lane >> 4) * 8;
    int bRow = (lane & 7) + (lane >> 4) * 8;
    int bCg  = ((lane >> 3) & 1) * 8;

    auto compute_stage = [&](int s) {
        uint32_t sBase = smBase + (uint32_t)(s * NT * TH * 2);
        #pragma unroll
        for (int ks = 0; ks < BK / 16; ks++) {
            uint32_t ah[2][4], al[2][4];
            #pragma unroll
            for (int mm = 0; mm < 2; mm++) {
                uint32_t addr = sBase + (uint32_t)(((warpM * 32 + mm * 16 + aRow) * PK + ks * 16 + aCg) * 2);
                LDSM4(ah[mm][0], ah[mm][1], ah[mm][2], ah[mm][3], addr);
                if (SPLIT_A) LDSM4(al[mm][0], al[mm][1], al[mm][2], al[mm][3], addr + TH * 2);
            }
            #pragma unroll
            for (int nn = 0; nn < 4; nn++) {
                uint32_t baddr = sBase + (uint32_t)(((NT - 1) * TH + (warpN * 64 + nn * 16 + bRow) * PK + ks * 16 + bCg) * 2);
                uint32_t bh[4];
                LDSM4(bh[0], bh[1], bh[2], bh[3], baddr);
                #pragma unroll
                for (int mm = 0; mm < 2; mm++) {
                    MMA16816(acc[mm][2 * nn],     ah[mm], bh[0], bh[1]);
                    MMA16816(acc[mm][2 * nn + 1], ah[mm], bh[2], bh[3]);
                    if (SPLIT_A) {
                        MMA16816(acc[mm][2 * nn],     al[mm], bh[0], bh[1]);
                        MMA16816(acc[mm][2 * nn + 1], al[mm], bh[2], bh[3]);
                    }
                }
            }
        }
    };

    load_stage(0, 0);
    CP_COMMIT();
    int bufC = 0, bufL = 1;
    for (int c = 0; c < nc; c++) {
        if (c + 1 < nc) {
            load_stage(c + 1, bufL);
            CP_COMMIT();
            asm volatile("cp.async.wait_group 1;" ::: "memory");
        } else {
            asm volatile("cp.async.wait_group 0;" ::: "memory");
        }
        __syncthreads();
        compute_stage(bufC);
        bufC = (bufC == 2) ? 0 : bufC + 1;
        bufL = (bufL == 2) ? 0 : bufL + 1;
    }

    // ---- epilogue (vectorized) ----
    if (MODE == 1) {
        #pragma unroll
        for (int mm = 0; mm < 2; mm++) {
            #pragma unroll
            for (int nf = 0; nf < 8; nf++) {
                int rr = rowBase + warpM * 32 + mm * 16 + (lane >> 2);
                int gc = colBase + warpN * 64 + nf * 8 + (lane & 3) * 2;
                int j  = gc >> 1;
                float bh_ = bias[j], bg_ = bias[FFd + j];
                float h0 = acc[mm][nf][0] + bh_;
                float g0 = acc[mm][nf][1] + bg_;
                Ch[(size_t)rr * ldc + j] = __float2half_rn(h0 * gelu_exact(g0));
                float h1 = acc[mm][nf][2] + bh_;
                float g1 = acc[mm][nf][3] + bg_;
                Ch[(size_t)(rr + 8) * ldc + j] = __float2half_rn(h1 * gelu_exact(g1));
            }
        }
    } else if (MODE == 2) {
        // M = BN exact, no row guard. gc even. Routes: q(half2,×alpha) | k | v (all half)
        half* vdst = (half*)C;
        #pragma unroll
        for (int mm = 0; mm < 2; mm++) {
            #pragma unroll
            for (int nf = 0; nf < 8; nf++) {
                int r  = rowBase + warpM * 32 + mm * 16 + (lane >> 2);
                int gc = colBase + warpN * 64 + nf * 8 + (lane & 3) * 2;
                #pragma unroll
                for (int p = 0; p < 2; p++) {
                    int rr = r + p * 8;
                    float v0 = acc[mm][nf][2 * p], v1 = acc[mm][nf][2 * p + 1];
                    if (gc < Ii)
                        *reinterpret_cast<half2*>(Ch + (size_t)rr * Ii + gc) =
                            __floats2half2_rn(v0 * alpha, v1 * alpha);
                    else if (gc < 2 * Ii)
                        *reinterpret_cast<half2*>(Ch2 + (size_t)rr * Ii + gc - Ii) =
                            __floats2half2_rn(v0, v1);
                    else
                        *reinterpret_cast<half2*>(vdst + (size_t)rr * Ii + gc - 2 * Ii) =
                            __floats2half2_rn(v0, v1);
                }
            }
        }
    } else if (MODE == 3) {
        #pragma unroll
        for (int mm = 0; mm < 2; mm++) {
            #pragma unroll
            for (int nf = 0; nf < 8; nf++) {
                int r  = rowBase + warpM * 32 + mm * 16 + (lane >> 2);
                int gc = colBase + warpN * 64 + nf * 8 + (lane & 3) * 2;
                #pragma unroll
                for (int p = 0; p < 2; p++) {
                    int rr = r + p * 8;
                    if (rr < M) {
                        float v0 = acc[mm][nf][2 * p], v1 = acc[mm][nf][2 * p + 1];
                        if (gc < Ii)
                            *reinterpret_cast<half2*>(Ch + (size_t)rr * Ii + gc) =
                                __floats2half2_rn(v0, v1);
                        else {
                            float2 f2 = make_float2(v0, v1);
                            *reinterpret_cast<float2*>(C + (size_t)rr * Ii + gc - Ii) = f2;
                        }
                    }
                }
            }
        }
    } else {
        #pragma unroll
        for (int mm = 0; mm < 2; mm++) {
            #pragma unroll
            for (int nf = 0; nf < 8; nf++) {
                int r  = rowBase + warpM * 32 + mm * 16 + (lane >> 2);
                int gc = colBase + warpN * 64 + nf * 8 + (lane & 3) * 2;
                #pragma unroll
                for (int p = 0; p < 2; p++) {
                    int rr = r + p * 8;
                    if (rr >= M) continue;
                    float v0 = acc[mm][nf][2 * p], v1 = acc[mm][nf][2 * p + 1];
                    size_t idx = (size_t)offC + (size_t)rr * ldc + gc;
                    if (gc + 1 < N) {
                        v0 *= alpha; v1 *= alpha;
                        if (bias) { v0 += bias[gc]; v1 += bias[gc + 1]; }
                        if (resid) {
                            float2 rv = *reinterpret_cast<const float2*>(resid + idx);
                            v0 += rv.x; v1 += rv.y;
                        }
                        if (C) *reinterpret_cast<float2*>(C + idx) = make_float2(v0, v1);
                        if (Ch) *reinterpret_cast<half2*>(Ch + idx) = __floats2half2_rn(v0, v1);
                    } else if (gc < N) {
                        v0 *= alpha;
                        if (bias) v0 += bias[gc];
                        if (resid) v0 += resid[idx];
                        if (C) C[idx] = v0;
                        if (Ch) Ch[idx] = __float2half_rn(v0);
                    }
                }
            }
        }
    }
}

#define SMEM_BK64  (3*2*(128*72)*2)   // 110592 B
#define SMEM_BK32S (3*3*(128*40)*2)   // 92160 B

// ---------------------------------------------------------------------------
// Fused flash self-attention. V loaded [key][d] fp16 (same layout as K),
// PV B-fragments via ldmatrix.trans. smem: Q | K s0,s1 | V s0,s1 (5 tiles).
// ---------------------------------------------------------------------------
#define FA_PITCH  72
#define FA_QT     (128*FA_PITCH)
#define FA_SMEM_BYTES (5*FA_QT*2)   // 92160 B

__global__ void __launch_bounds__(256) flash_attn(
    const half* __restrict__ qh, const half* __restrict__ kh,
    const half* __restrict__ vh, half* __restrict__ atth)
{
    extern __shared__ half sm[];
    uint32_t smBase = smem_u32(sm);
    int tid = threadIdx.x, lane = tid & 31, wid = tid >> 5;

    int bh = blockIdx.y;
    int b = bh >> 4, h = bh & 15;
    int q0 = blockIdx.x * 128;
    int qg0 = b * Ntok + q0;
    int kg0 = b * Ntok;
    int hcol = h * 64;

    auto ldQ = [&]() {
        #pragma unroll
        for (int i = 0; i < 4; i++) {
            int seg = tid + (i << 8);
            int row = seg >> 3;
            int cs = (seg & 7) << 3;
            const half* src = qh + (size_t)(qg0 + row) * Ii + hcol + cs;
            uint32_t dst = smBase + (uint32_t)((row * FA_PITCH + cs) * 2);
            CP_ASYNC16(dst, src);
        }
    };
    auto ldKV = [&](int chunk, int s) {
        int key0 = chunk << 7;
        #pragma unroll
        for (int i = 0; i < 8; i++) {
            int seg = tid + (i << 8);
            int t = seg >> 10;                  // 0 K, 1 V
            int w = seg & 1023;
            int row = w >> 3;
            int cs = (w & 7) << 3;
            const half* src = (t ? vh : kh) + (size_t)(kg0 + key0 + row) * Ii + hcol + cs;
            uint32_t dst = smBase + (uint32_t)((FA_QT * (1 + 2 * t + s) + row * FA_PITCH + cs) * 2);
            CP_ASYNC16(dst, src);
        }
    };

    int aRow = (lane & 7) + ((lane >> 3) & 1) * 8;
    int aCg  = (lane >> 4) * 8;
    int bRow = (lane & 7) + (lane >> 4) * 8;
    int bCg  = ((lane >> 3) & 1) * 8;
    int vRow = lane & 15;                // trans-ldsm: k row
    int vCg  = (lane >> 4) << 3;         // trans-ldsm: +8 d offset

    float O[8][4];
    #pragma unroll
    for (int i = 0; i < 8; i++)
        #pragma unroll
        for (int e = 0; e < 4; e++) O[i][e] = 0.f;
    float M0 = -1e30f, M1 = -1e30f, L0 = 0.f, L1 = 0.f;

    ldQ(); ldKV(0, 0);
    CP_COMMIT();
    ldKV(1, 1);
    CP_COMMIT();

    for (int c = 0; c < 16; c++) {
        if (c < 15) asm volatile("cp.async.wait_group 1;" ::: "memory");
        else        asm volatile("cp.async.wait_group 0;" ::: "memory");
        __syncthreads();

        int s = c & 1;
        float S[16][4];
        #pragma unroll
        for (int i = 0; i < 16; i++)
            #pragma unroll
            for (int e = 0; e < 4; e++) S[i][e] = 0.f;

        uint32_t kTile = smBase + (uint32_t)(FA_QT * (1 + s) * 2);
        #pragma unroll
        for (int ks = 0; ks < 4; ks++) {
            uint32_t aH[4];
            uint32_t addrA = smBase + (uint32_t)(((wid * 16 + aRow) * FA_PITCH + ks * 16 + aCg) * 2);
            LDSM4(aH[0], aH[1], aH[2], aH[3], addrA);
            #pragma unroll
            for (int nn = 0; nn < 8; nn++) {
                uint32_t addrB = kTile + (uint32_t)(((nn * 16 + bRow) * FA_PITCH + ks * 16 + bCg) * 2);
                uint32_t bH[4];
                LDSM4(bH[0], bH[1], bH[2], bH[3], addrB);
                MMA16816(S[2 * nn],     aH, bH[0], bH[1]);
                MMA16816(S[2 * nn + 1], aH, bH[2], bH[3]);
            }
        }

        float cm0 = -1e30f, cm1 = -1e30f;
        #pragma unroll
        for (int i = 0; i < 16; i++) {
            cm0 = fmaxf(cm0, fmaxf(S[i][0], S[i][1]));
            cm1 = fmaxf(cm1, fmaxf(S[i][2], S[i][3]));
        }
        #pragma unroll
        for (int o = 1; o <= 2; o <<= 1) {
            cm0 = fmaxf(cm0, __shfl_xor_sync(0xffffffffu, cm0, o));
            cm1 = fmaxf(cm1, __shfl_xor_sync(0xffffffffu, cm1, o));
        }
        float nM0 = fmaxf(M0, cm0), nM1 = fmaxf(M1, cm1);
        float f0 = __expf(M0 - nM0), f1 = __expf(M1 - nM1);
        M0 = nM0; M1 = nM1;
        #pragma unroll
        for (int i = 0; i < 8; i++) {
            O[i][0] *= f0; O[i][1] *= f0; O[i][2] *= f1; O[i][3] *= f1;
        }
        float l0 = 0.f, l1 = 0.f;
        #pragma unroll
        for (int i = 0; i < 16; i++) {
            S[i][0] = __expf(S[i][0] - nM0);
            S[i][1] = __expf(S[i][1] - nM0);
            S[i][2] = __expf(S[i][2] - nM1);
            S[i][3] = __expf(S[i][3] - nM1);
            l0 += S[i][0] + S[i][1];
            l1 += S[i][2] + S[i][3];
        }
        #pragma unroll
        for (int o = 1; o <= 2; o <<= 1) {
            l0 += __shfl_xor_sync(0xffffffffu, l0, o);
            l1 += __shfl_xor_sync(0xffffffffu, l1, o);
        }
        L0 = L0 * f0 + l0;
        L1 = L1 * f1 + l1;

        // ---- O += P @ V (V [key][d], trans-ldsm B fragments) ----
        uint32_t vTile = smBase + (uint32_t)(FA_QT * (3 + s) * 2);
        #pragma unroll
        for (int kk = 0; kk < 8; kk++) {
            uint32_t PhF[4];
            #pragma unroll
            for (int u = 0; u < 2; u++) {
                int t = 2 * kk + u;
                half2 h01 = __floats2half2_rn(S[t][0], S[t][1]);
                half2 h23 = __floats2half2_rn(S[t][2], S[t][3]);
                PhF[2 * u]     = *reinterpret_cast<uint32_t*>(&h01);
                PhF[2 * u + 1] = *reinterpret_cast<uint32_t*>(&h23);
            }
            #pragma unroll
            for (int nn = 0; nn < 4; nn++) {
                uint32_t addrV = vTile + (uint32_t)(((kk * 16 + vRow) * FA_PITCH + nn * 16 + vCg) * 2);
                uint32_t vF[4];
                LDSM4T(vF[0], vF[1], vF[2], vF[3], addrV);
                MMA16816(O[2 * nn],     PhF, vF[0], vF[1]);
                MMA16816(O[2 * nn + 1], PhF, vF[2], vF[3]);
            }
        }

        __syncthreads();
        if (c + 2 < 16) { ldKV(c + 2, s); CP_COMMIT(); }
    }

    float inv0 = 1.f / L0, inv1 = 1.f / L1;
    int r0 = qg0 + wid * 16 + (lane >> 2);
    int r1 = r0 + 8;
    #pragma unroll
    for (int nf = 0; nf < 8; nf++) {
        int d0 = nf * 8 + (lane & 3) * 2;
        *reinterpret_cast<half2*>(atth + (size_t)r0 * Ii + hcol + d0) =
            __floats2half2_rn(O[nf][0] * inv0, O[nf][1] * inv0);
        *reinterpret_cast<half2*>(atth + (size_t)r1 * Ii + hcol + d0) =
            __floats2half2_rn(O[nf][2] * inv1, O[nf][3] * inv1);
    }
}

// ---------------------------------------------------------------------------
// LayerNorm -> fp16
// ---------------------------------------------------------------------------
__global__ __launch_bounds__(256) void ln_kernel(
    const float* __restrict__ x, const float* __restrict__ g, const float* __restrict__ b,
    half* __restrict__ oh)
{
    size_t row = blockIdx.x;
    const float* xr = x + row * Dm;
    __shared__ float red[256];
    int t = threadIdx.x;
    float v[4];
    float s = 0.f;
    #pragma unroll
    for (int j = 0; j < 4; j++) { v[j] = xr[t + j * 256]; s += v[j]; }
    red[t] = s; __syncthreads();
    for (int o = 128; o > 0; o >>= 1) { if (t < o) red[t] += red[t + o]; __syncthreads(); }
    float mean = red[0] * (1.f / Dm);
    __syncthreads();
    float s2 = 0.f;
    #pragma unroll
    for (int j = 0; j < 4; j++) { float d = v[j] - mean; s2 += d * d; }
    red[t] = s2; __syncthreads();
    for (int o = 128; o > 0; o >>= 1) { if (t < o) red[t] += red[t + o]; __syncthreads(); }
    float inv = rsqrtf(red[0] * (1.f / Dm) + 1e-5f);
    #pragma unroll
    for (int j = 0; j < 4; j++) {
        int i = t + j * 256;
        oh[row * Dm + i] = __float2half_rn((v[j] - mean) * inv * g[i] + b[i]);
    }
}

// ---------------------------------------------------------------------------
// Softmax -> split fp16 (cross-attn)
// ---------------------------------------------------------------------------
__global__ __launch_bounds__(256) void softmax_split_kernel(
    const float* __restrict__ s, half* __restrict__ ph, half* __restrict__ pl,
    int cols, int ldin, int ldout)
{
    size_t row = blockIdx.x;
    const float* r = s + row * (size_t)ldin;
    __shared__ float red[256];
    int t = threadIdx.x;
    float v = (t < cols) ? r[t] : -INFINITY;
    red[t] = v; __syncthreads();
    for (int o = 128; o > 0; o >>= 1) { if (t < o) red[t] = fmaxf(red[t], red[t + o]); __syncthreads(); }
    float m = red[0]; __syncthreads();
    float e = (t < cols) ? __expf(v - m) : 0.f;
    red[t] = e; __syncthreads();
    for (int o = 128; o > 0; o >>= 1) { if (t < o) red[t] += red[t + o]; __syncthreads(); }
    float inv = 1.f / red[0];
    if (t < ldout) {
        half h, l; split2(e * inv, h, l);
        ph[row * (size_t)ldout + t] = h;
        pl[row * (size_t)ldout + t] = l;
    }
}

// ---------------------------------------------------------------------------
// Plain fp32 -> fp16
// ---------------------------------------------------------------------------
__global__ __launch_bounds__(256) void tohalf_kernel(
    const float* __restrict__ src, half* __restrict__ dh, long long n)
{
    long long i = (long long)blockIdx.x * 256 + threadIdx.x;
    if (i >= n) return;
    dh[i] = __float2half_rn(src[i]);
}

// ---------------------------------------------------------------------------
// Unified fast weight transpose (unchanged)
// ---------------------------------------------------------------------------
#define NSEG 10
struct TransDesc {
    const float* src[NSEG];
    half*        dst[NSEG];
    int R[NSEG], C[NSEG], start[NSEG], inter[NSEG];
};

__global__ __launch_bounds__(256) void multi_transpose(TransDesc d)
{
    __shared__ float tile[64][65];
    int bid = blockIdx.x;
    int s = 0;
    #pragma unroll
    for (int i = 1; i < NSEG; i++) if (bid >= d.start[i]) s = i;
    int local = bid - d.start[s];
    int R = d.R[s], C = d.C[s];
    int Rb = R >> 6;
    int r0 = (local % Rb) << 6;
    int c0 = (local / Rb) << 6;
    const float* src = d.src[s];
    half* dst = d.dst[s];
    int t = threadIdx.x;

    #pragma unroll
    for (int i = 0; i < 4; i++) {
        int idx = t + (i << 8);
        int row = idx >> 4;
        int col = (idx & 15) << 2;
        float4 v = *reinterpret_cast<const float4*>(src + (size_t)(r0 + row) * C + c0 + col);
        tile[row][col] = v.x; tile[row][col + 1] = v.y;
        tile[row][col + 2] = v.z; tile[row][col + 3] = v.w;
    }
    __syncthreads();

    bool inter = d.inter[s] != 0;
    #pragma unroll
    for (int i = 0; i < 4; i++) {
        int idx = t + (i << 8);
        int ccL = idx >> 4;
        int rr  = (idx & 15) << 2;
        int cc  = c0 + ccL;
        half hv[4];
        #pragma unroll
        for (int j = 0; j < 4; j++) hv[j] = __float2half_rn(tile[rr + j][ccL]);
        size_t orow = inter ? ((cc < FFd) ? (size_t)(2 * cc) : (size_t)(2 * (cc - FFd) + 1))
                            : (size_t)cc;
        *reinterpret_cast<uint2*>(dst + orow * R + r0 + rr) = *reinterpret_cast<uint2*>(hv);
    }
}

// ---------------------------------------------------------------------------
// Per-head V transpose (cross only), 64x64 vectorized
// ---------------------------------------------------------------------------
__global__ __launch_bounds__(256) void head_t64_kernel(
    const float* __restrict__ src, half* __restrict__ dst, int T, int Tpad)
{
    __shared__ float tile[64][65];
    int zh = blockIdx.z;
    int b = zh >> 4, h = zh & 15;
    int t0 = blockIdx.x * 64;
    int t = threadIdx.x;

    #pragma unroll
    for (int i = 0; i < 4; i++) {
        int idx = t + (i << 8);
        int row = idx >> 4;
        int col = (idx & 15) << 2;
        int tok = t0 + row;
        float4 v = make_float4(0.f, 0.f, 0.f, 0.f);
        if (tok < T)
            v = *reinterpret_cast<const float4*>(src + ((size_t)b * T + tok) * 1024 + h * 64 + col);
        tile[row][col] = v.x; tile[row][col + 1] = v.y;
        tile[row][col + 2] = v.z; tile[row][col + 3] = v.w;
    }
    __syncthreads();

    size_t base = (size_t)zh * 64 * Tpad;
    #pragma unroll
    for (int i = 0; i < 4; i++) {
        int idx = t + (i << 8);
        int dL = idx >> 4;
        int tt = (idx & 15) << 2;
        int tok = t0 + tt;
        if (tok + 3 < Tpad) {
            half hv[4];
            #pragma unroll
            for (int j = 0; j < 4; j++) hv[j] = __float2half_rn(tile[tt + j][dL]);
            *reinterpret_cast<uint2*>(dst + base + (size_t)dL * Tpad + tok) = *reinterpret_cast<uint2*>(hv);
        } else if (tok < Tpad) {
            for (int j = 0; j < 4 && tok + j < Tpad; j++)
                dst[base + (size_t)dL * Tpad + tok + j] = __float2half_rn(tile[tt + j][dL]);
        }
    }
}

// ---------------------------------------------------------------------------
// Orchestration
// ---------------------------------------------------------------------------
static inline dim3 ggrid(int M, int N, int z) { return dim3((N + 127) / 128, (M + 127) / 128, z); }

#define SYM(p, s) cudaGetSymbolAddress((void**)&p, s)

extern "C" void kernel_launch(void* const* d_in, const int* in_sizes, int n_in,
                              void* d_out, int out_size)
{
    const float* x     = (const float*)d_in[0];
    const float* ctx   = (const float*)d_in[1];
    const float* ln1_g = (const float*)d_in[2];
    const float* ln1_b = (const float*)d_in[3];
    const float* ln2_g = (const float*)d_in[4];
    const float* ln2_b = (const float*)d_in[5];
    const float* ln3_g = (const float*)d_in[6];
    const float* ln3_b = (const float*)d_in[7];
    const float* Wq1   = (const float*)d_in[8];
    const float* Wk1   = (const float*)d_in[9];
    const float* Wv1   = (const float*)d_in[10];
    const float* Wo1   = (const float*)d_in[11];
    const float* bo1   = (const float*)d_in[12];
    const float* Wq2   = (const float*)d_in[13];
    const float* Wk2   = (const float*)d_in[14];
    const float* Wv2   = (const float*)d_in[15];
    const float* Wo2   = (const float*)d_in[16];
    const float* bo2   = (const float*)d_in[17];
    const float* Wff1  = (const float*)d_in[18];
    const float* bff1  = (const float*)d_in[19];
    const float* Wff2  = (const float*)d_in[20];
    const float* bff2  = (const float*)d_in[21];
    float* out = (float*)d_out;

    half *lnh,*qh,*kh,*vh,*vth,*Ph,*Pl,*atth,*ctxh,*ffh;
    half *wqkv1,*wo1h,*wq2h,*wkv2,*wo2h,*wf1h,*wf2h;
    float *v,*sim,*x1,*x2;
    SYM(lnh,g_lnh); SYM(qh,g_qh); SYM(kh,g_kh); SYM(vh,g_vh);
    SYM(v,g_v); SYM(vth,g_vth); SYM(sim,g_sim); SYM(Ph,g_Ph); SYM(Pl,g_Pl);
    SYM(atth,g_atth); SYM(x1,g_x1); SYM(x2,g_x2);
    SYM(ctxh,g_ctxh); SYM(ffh,g_ffh);
    SYM(wqkv1,g_wqkv1); SYM(wo1h,g_wo1h); SYM(wq2h,g_wq2h); SYM(wkv2,g_wkv2);
    SYM(wo2h,g_wo2h); SYM(wf1h,g_wf1h); SYM(wf2h,g_wf2h);

    cudaFuncSetAttribute((const void*)mma_gemm<0,0,64>, cudaFuncAttributeMaxDynamicSharedMemorySize, SMEM_BK64);
    cudaFuncSetAttribute((const void*)mma_gemm<0,1,64>, cudaFuncAttributeMaxDynamicSharedMemorySize, SMEM_BK64);
    cudaFuncSetAttribute((const void*)mma_gemm<0,2,64>, cudaFuncAttributeMaxDynamicSharedMemorySize, SMEM_BK64);
    cudaFuncSetAttribute((const void*)mma_gemm<0,3,64>, cudaFuncAttributeMaxDynamicSharedMemorySize, SMEM_BK64);
    cudaFuncSetAttribute((const void*)mma_gemm<1,0,32>, cudaFuncAttributeMaxDynamicSharedMemorySize, SMEM_BK32S);
    cudaFuncSetAttribute((const void*)flash_attn, cudaFuncAttributeMaxDynamicSharedMemorySize, FA_SMEM_BYTES);

    // ---- single fused weight-transpose launch ----
    TransDesc td;
    int pos = 0, si = 0;
    auto addSeg = [&](const float* s, half* dd, int R, int C, int inter) {
        td.src[si] = s; td.dst[si] = dd; td.R[si] = R; td.C[si] = C;
        td.start[si] = pos; td.inter[si] = inter;
        pos += (R >> 6) * (C >> 6);
        si++;
    };
    addSeg(Wq1,  wqkv1,                    Dm,  Ii,     0);
    addSeg(Wk1,  wqkv1 + (size_t)Ii*Dm,   Dm,  Ii,     0);
    addSeg(Wv1,  wqkv1 + (size_t)2*Ii*Dm, Dm,  Ii,     0);
    addSeg(Wo1,  wo1h,                     Ii,  Dm,     0);
    addSeg(Wq2,  wq2h,                     Dm,  Ii,     0);
    addSeg(Wk2,  wkv2,                     DCc, Ii,     0);
    addSeg(Wv2,  wkv2 + (size_t)Ii*DCc,   DCc, Ii,     0);
    addSeg(Wo2,  wo2h,                     Ii,  Dm,     0);
    addSeg(Wff2, wf2h,                     FFd, Dm,     0);
    addSeg(Wff1, wf1h,                     Dm,  2*FFd,  1);
    multi_transpose<<<pos, 256>>>(td);
    tohalf_kernel<<<(BM2*DCc + 255)/256, 256>>>(ctx, ctxh, (long long)BM2*DCc);

    // ================= block 1: self-attention =================
    ln_kernel<<<BN, 256>>>(x, ln1_g, ln1_b, lnh);

    // fused QKV: q(×SCALE)->qh, k->kh, v->vh (fp16, flash layout)
    mma_gemm<0,2,64><<<ggrid(BN, 3*Ii, 1), 256, SMEM_BK64>>>(lnh, nullptr, wqkv1, nullptr, nullptr,
        (float*)vh, qh, kh, BN, 3*Ii, Dm, Dm, Dm, Ii, 0,0,0,0,0,0, 1, SCALE);

    flash_attn<<<dim3(Ntok/128, BHh), 256, FA_SMEM_BYTES>>>(qh, kh, vh, atth);

    mma_gemm<0,0,64><<<ggrid(BN, Dm, 1), 256, SMEM_BK64>>>(atth, nullptr, wo1h, bo1, x,
        x1, nullptr, nullptr, BN, Dm, Ii, Ii, Ii, Dm, 0,0,0,0,0,0, 1, 1.f);

    // ================= block 2: cross-attention =================
    ln_kernel<<<BN, 256>>>(x1, ln2_g, ln2_b, lnh);

    mma_gemm<0,0,64><<<ggrid(BN, Ii, 1), 256, SMEM_BK64>>>(lnh, nullptr, wq2h, nullptr, nullptr,
        nullptr, qh, nullptr, BN, Ii, Dm, Dm, Dm, Ii, 0,0,0,0,0,0, 1, SCALE);

    mma_gemm<0,3,64><<<ggrid(BM2, 2*Ii, 1), 256, SMEM_BK64>>>(ctxh, nullptr, wkv2, nullptr, nullptr,
        v, kh, nullptr, BM2, 2*Ii, DCc, DCc, DCc, Ii, 0,0,0,0,0,0, 1, 1.f);

    head_t64_kernel<<<dim3((MctxP+63)/64, 1, BHh), 256>>>(v, vth, Mctx, MctxP);

    mma_gemm<0,0,64><<<ggrid(Ntok, Mctx, BHh), 256, SMEM_BK64>>>(qh, nullptr, kh, nullptr, nullptr,
        sim, nullptr, nullptr, Ntok, Mctx, DHd, Ii, Ii, MctxP,
        (long long)Ntok*Ii, 64, (long long)Mctx*Ii, 64,
        (long long)Hh*Ntok*MctxP, (long long)Ntok*MctxP, Hh, 1.f);

    softmax_split_kernel<<<BHh*Ntok, 256>>>(sim, Ph, Pl, Mctx, MctxP, MctxP);

    mma_gemm<1,0,32><<<ggrid(Ntok, DHd, BHh), 256, SMEM_BK32S>>>(Ph, Pl, vth, nullptr, nullptr,
        nullptr, atth, nullptr, Ntok, DHd, MctxP, MctxP, MctxP, Ii,
        (long long)Hh*Ntok*MctxP, (long long)Ntok*MctxP,
        (long long)Hh*DHd*MctxP, (long long)DHd*MctxP,
        (long long)Ntok*Ii, 64, Hh, 1.f);

    mma_gemm<0,0,64><<<ggrid(BN, Dm, 1), 256, SMEM_BK64>>>(atth, nullptr, wo2h, bo2, x1,
        x2, nullptr, nullptr, BN, Dm, Ii, Ii, Ii, Dm, 0,0,0,0,0,0, 1, 1.f);

    // ================= block 3: GEGLU FF =================
    ln_kernel<<<BN, 256>>>(x2, ln3_g, ln3_b, lnh);

    mma_gemm<0,1,64><<<ggrid(BN, 2*FFd, 1), 256, SMEM_BK64>>>(lnh, nullptr, wf1h, bff1, nullptr,
        nullptr, ffh, nullptr, BN, 2*FFd, Dm, Dm, Dm, FFd, 0,0,0,0,0,0, 1, 1.f);

    mma_gemm<0,0,64><<<ggrid(BN, Dm, 1), 256, SMEM_BK64>>>(ffh, nullptr, wf2h, bff2, x2,
        out, nullptr, nullptr, BN, Dm, FFd, FFd, FFd, Dm, 0,0,0,0,0,0, 1, 1.f);
}

// round 15
// speedup vs baseline: 1.5311x; 1.5311x over previous
#include <cuda_runtime.h>
#include <cuda_fp16.h>
#include <math.h>
#include <stdint.h>

// ---------------------------------------------------------------------------
// Problem constants
// ---------------------------------------------------------------------------
#define Bsz   2
#define Ntok  2048
#define Dm    1024
#define Hh    16
#define DHd   64
#define Ii    1024
#define DCc   768
#define Mctx  77
#define MctxP 80
#define FFd   4096
#define BN    (Bsz*Ntok)
#define BM2   (Bsz*Mctx)
#define BHh   (Bsz*Hh)
#define SCALE 0.125f

// ---------------------------------------------------------------------------
// Device scratch
// ---------------------------------------------------------------------------
#define DEVARR(name, type, count) __device__ __align__(16) type name[(size_t)(count)]

DEVARR(g_lnh,  half, BN*Dm);
DEVARR(g_qh,   half, BN*Ii);
DEVARR(g_kh,   half, BN*Ii);
DEVARR(g_v,    float, BN*Ii);
DEVARR(g_vth,  half, BHh*DHd*Ntok);
DEVARR(g_sim,  float, (size_t)BHh*Ntok*MctxP);
DEVARR(g_Ph,   half, (size_t)BHh*Ntok*MctxP); DEVARR(g_Pl, half, (size_t)BHh*Ntok*MctxP);
DEVARR(g_atth, half, BN*Ii);
DEVARR(g_x1,   float, BN*Dm);  DEVARR(g_x2,   float, BN*Dm);
DEVARR(g_ctxh, half, BM2*DCc);
DEVARR(g_ffh,  half, (size_t)BN*FFd);
// transposed weights [N x K], hi only
DEVARR(g_wqkv1, half, (size_t)3*Dm*Ii);
DEVARR(g_wo1h,  half, Dm*Ii);
DEVARR(g_wq2h,  half, Dm*Ii);
DEVARR(g_wkv2,  half, (size_t)2*Ii*DCc);
DEVARR(g_wo2h,  half, Dm*Ii);
DEVARR(g_wf1h,  half, (size_t)Dm*2*FFd);   // interleaved: row 2j=h, 2j+1=gate
DEVARR(g_wf2h,  half, (size_t)FFd*Dm);

// ---------------------------------------------------------------------------
// Helpers
// ---------------------------------------------------------------------------
__device__ __forceinline__ uint32_t smem_u32(const void* p) {
    uint32_t a;
    asm("{ .reg .u64 t; cvta.to.shared.u64 t, %1; cvt.u32.u64 %0, t; }" : "=r"(a) : "l"(p));
    return a;
}
__device__ __forceinline__ void split2(float x, half& h, half& l) {
    h = __float2half_rn(x);
    l = __float2half_rn(x - __half2float(h));
}
__device__ __forceinline__ float gelu_exact(float g) {
    return 0.5f * g * (1.f + erff(g * 0.70710678118654752440f));
}

#define LDSM4(r0, r1, r2, r3, addr) \
    asm volatile("ldmatrix.sync.aligned.m8n8.x4.shared.b16 {%0,%1,%2,%3}, [%4];" \
        : "=r"(r0), "=r"(r1), "=r"(r2), "=r"(r3) : "r"(addr))

#define MMA16816(c, a, b0, b1) \
    asm volatile("mma.sync.aligned.m16n8k16.row.col.f32.f16.f16.f32 " \
        "{%0,%1,%2,%3}, {%4,%5,%6,%7}, {%8,%9}, {%0,%1,%2,%3};" \
        : "+f"((c)[0]), "+f"((c)[1]), "+f"((c)[2]), "+f"((c)[3]) \
        : "r"((a)[0]), "r"((a)[1]), "r"((a)[2]), "r"((a)[3]), "r"(b0), "r"(b1))

#define CP_ASYNC16(dst, src) \
    asm volatile("cp.async.cg.shared.global [%0], [%1], 16;" :: "r"(dst), "l"(src) : "memory")
#define CP_COMMIT() asm volatile("cp.async.commit_group;" ::: "memory")

// ---------------------------------------------------------------------------
// mma.sync GEMM: acc = A @ Bh^T, 128x128 tile, 8 warps.
// 3-buffer rotation, depth-1 prefetch, ONE __syncthreads per stage.
// MODE 0: C/Ch = alpha*acc (+bias)(+resid); 1: GEGLU; 2: QKV route; 3: KV route
// ---------------------------------------------------------------------------
template<int SPLIT_A, int MODE, int BK>
__global__ void __launch_bounds__(256, 2) mma_gemm(
    const half* __restrict__ Ah_, const half* __restrict__ Al_,
    const half* __restrict__ Bh_,
    const float* __restrict__ bias, const float* __restrict__ resid,
    float* __restrict__ C, half* __restrict__ Ch, half* __restrict__ Ch2,
    int M, int N, int K, int lda, int ldb, int ldc,
    long long aO, long long aI, long long bO, long long bI,
    long long cO, long long cI, int nInner, float alpha)
{
    constexpr int NT  = 2 + SPLIT_A;
    constexpr int PK  = BK + 8;
    constexpr int TH  = 128 * PK;
    constexpr int SPT = 128 * (BK / 8);
    constexpr int ITR = NT * SPT / 256;

    extern __shared__ half sm[];
    uint32_t smBase = smem_u32(sm);
    int tid = threadIdx.x, lane = tid & 31, wid = tid >> 5;
    int warpM = wid >> 1, warpN = wid & 1;

    int z = blockIdx.z, zo = z / nInner, zi = z % nInner;
    const half* Ahp = Ah_ + (long long)zo * aO + (long long)zi * aI;
    const half* Alp = SPLIT_A ? (Al_ + (long long)zo * aO + (long long)zi * aI) : nullptr;
    const half* Bhp = Bh_ + (long long)zo * bO + (long long)zi * bI;
    long long offC = (long long)zo * cO + (long long)zi * cI;

    int rowBase = blockIdx.y * 128, colBase = blockIdx.x * 128;

    float acc[2][8][4];
    #pragma unroll
    for (int i = 0; i < 2; i++)
        #pragma unroll
        for (int j = 0; j < 8; j++)
            #pragma unroll
            for (int e = 0; e < 4; e++) acc[i][j][e] = 0.f;

    int nc = (K + BK - 1) / BK;

    auto load_stage = [&](int c, int s) {
        int k0 = c * BK;
        #pragma unroll
        for (int i = 0; i < ITR; i++) {
            int seg  = tid + (i << 8);
            int tile = seg / SPT;
            int w    = seg % SPT;
            int row  = w / (BK / 8);
            int cs   = (w % (BK / 8)) << 3;
            bool isA = tile < (NT - 1);
            const half* base = (tile == 0) ? Ahp : (SPLIT_A && tile == 1) ? Alp : Bhp;
            int ld  = isA ? lda : ldb;
            int gr  = (isA ? rowBase : colBase) + row;
            int gk  = k0 + cs;
            bool ok = (gr < (isA ? M : N)) && (gk + 8 <= K);
            const half* src = ok ? (base + (size_t)gr * ld + gk) : base;
            uint32_t dst = smBase + (uint32_t)(((s * NT + tile) * TH + row * PK + cs) * 2);
            uint32_t sz = ok ? 16u : 0u;
            asm volatile("cp.async.cg.shared.global [%0], [%1], 16, %2;"
                         :: "r"(dst), "l"(src), "r"(sz) : "memory");
        }
    };

    int aRow = (lane & 7) + ((lane >> 3) & 1) * 8;
    int aCg  = (lane >> 4) * 8;
    int bRow = (lane & 7) + (lane >> 4) * 8;
    int bCg  = ((lane >> 3) & 1) * 8;

    auto compute_stage = [&](int s) {
        uint32_t sBase = smBase + (uint32_t)(s * NT * TH * 2);
        #pragma unroll
        for (int ks = 0; ks < BK / 16; ks++) {
            uint32_t ah[2][4], al[2][4];
            #pragma unroll
            for (int mm = 0; mm < 2; mm++) {
                uint32_t addr = sBase + (uint32_t)(((warpM * 32 + mm * 16 + aRow) * PK + ks * 16 + aCg) * 2);
                LDSM4(ah[mm][0], ah[mm][1], ah[mm][2], ah[mm][3], addr);
                if (SPLIT_A) LDSM4(al[mm][0], al[mm][1], al[mm][2], al[mm][3], addr + TH * 2);
            }
            #pragma unroll
            for (int nn = 0; nn < 4; nn++) {
                uint32_t baddr = sBase + (uint32_t)(((NT - 1) * TH + (warpN * 64 + nn * 16 + bRow) * PK + ks * 16 + bCg) * 2);
                uint32_t bh[4];
                LDSM4(bh[0], bh[1], bh[2], bh[3], baddr);
                #pragma unroll
                for (int mm = 0; mm < 2; mm++) {
                    MMA16816(acc[mm][2 * nn],     ah[mm], bh[0], bh[1]);
                    MMA16816(acc[mm][2 * nn + 1], ah[mm], bh[2], bh[3]);
                    if (SPLIT_A) {
                        MMA16816(acc[mm][2 * nn],     al[mm], bh[0], bh[1]);
                        MMA16816(acc[mm][2 * nn + 1], al[mm], bh[2], bh[3]);
                    }
                }
            }
        }
    };

    load_stage(0, 0);
    CP_COMMIT();
    int bufC = 0, bufL = 1;
    for (int c = 0; c < nc; c++) {
        if (c + 1 < nc) {
            load_stage(c + 1, bufL);
            CP_COMMIT();
            asm volatile("cp.async.wait_group 1;" ::: "memory");
        } else {
            asm volatile("cp.async.wait_group 0;" ::: "memory");
        }
        __syncthreads();
        compute_stage(bufC);
        bufC = (bufC == 2) ? 0 : bufC + 1;
        bufL = (bufL == 2) ? 0 : bufL + 1;
    }

    if (MODE == 1) {
        #pragma unroll
        for (int mm = 0; mm < 2; mm++) {
            #pragma unroll
            for (int nf = 0; nf < 8; nf++) {
                int rr = rowBase + warpM * 32 + mm * 16 + (lane >> 2);
                int gc = colBase + warpN * 64 + nf * 8 + (lane & 3) * 2;
                int j  = gc >> 1;
                float bh_ = bias[j], bg_ = bias[FFd + j];
                float h0 = acc[mm][nf][0] + bh_;
                float g0 = acc[mm][nf][1] + bg_;
                Ch[(size_t)rr * ldc + j] = __float2half_rn(h0 * gelu_exact(g0));
                float h1 = acc[mm][nf][2] + bh_;
                float g1 = acc[mm][nf][3] + bg_;
                Ch[(size_t)(rr + 8) * ldc + j] = __float2half_rn(h1 * gelu_exact(g1));
            }
        }
    } else if (MODE == 2 || MODE == 3) {
        #pragma unroll
        for (int mm = 0; mm < 2; mm++) {
            #pragma unroll
            for (int nf = 0; nf < 8; nf++) {
                int r  = rowBase + warpM * 32 + mm * 16 + (lane >> 2);
                int cc = colBase + warpN * 64 + nf * 8 + (lane & 3) * 2;
                #pragma unroll
                for (int e = 0; e < 4; e++) {
                    int rr = r + (e >> 1) * 8;
                    int gc = cc + (e & 1);
                    if (rr < M) {
                        float val = acc[mm][nf][e];
                        if (MODE == 2) {
                            if (gc < Ii)
                                Ch[(size_t)rr * Ii + gc] = __float2half_rn(val * alpha);
                            else if (gc < 2 * Ii)
                                Ch2[(size_t)rr * Ii + gc - Ii] = __float2half_rn(val);
                            else
                                C[(size_t)rr * Ii + gc - 2 * Ii] = val;
                        } else {
                            if (gc < Ii)
                                Ch[(size_t)rr * Ii + gc] = __float2half_rn(val);
                            else
                                C[(size_t)rr * Ii + gc - Ii] = val;
                        }
                    }
                }
            }
        }
    } else {
        // MODE 0: vectorized (float2/half2) with N edge guard
        #pragma unroll
        for (int mm = 0; mm < 2; mm++) {
            #pragma unroll
            for (int nf = 0; nf < 8; nf++) {
                int r  = rowBase + warpM * 32 + mm * 16 + (lane >> 2);
                int gc = colBase + warpN * 64 + nf * 8 + (lane & 3) * 2;
                #pragma unroll
                for (int p = 0; p < 2; p++) {
                    int rr = r + p * 8;
                    if (rr >= M) continue;
                    float v0 = acc[mm][nf][2 * p], v1 = acc[mm][nf][2 * p + 1];
                    size_t idx = (size_t)offC + (size_t)rr * ldc + gc;
                    if (gc + 1 < N) {
                        v0 *= alpha; v1 *= alpha;
                        if (bias) { v0 += bias[gc]; v1 += bias[gc + 1]; }
                        if (resid) {
                            float2 rv = *reinterpret_cast<const float2*>(resid + idx);
                            v0 += rv.x; v1 += rv.y;
                        }
                        if (C) *reinterpret_cast<float2*>(C + idx) = make_float2(v0, v1);
                        if (Ch) *reinterpret_cast<half2*>(Ch + idx) = __floats2half2_rn(v0, v1);
                    } else if (gc < N) {
                        v0 *= alpha;
                        if (bias) v0 += bias[gc];
                        if (resid) v0 += resid[idx];
                        if (C) C[idx] = v0;
                        if (Ch) Ch[idx] = __float2half_rn(v0);
                    }
                }
            }
        }
    }
}

#define SMEM_BK64  (3*2*(128*72)*2)   // 110592 B
#define SMEM_BK32S (3*3*(128*40)*2)   // 92160 B

// ---------------------------------------------------------------------------
// Fused flash self-attention (round-13 version, V [d][key] + plain ldsm).
// ---------------------------------------------------------------------------
#define FA_PITCH  72
#define FA_VPITCH 136
#define FA_QT     (128*FA_PITCH)
#define FA_VT     (64*FA_VPITCH)
#define FA_KBASE  (FA_QT)
#define FA_VBASE  (3*FA_QT)
#define FA_SMEM_BYTES ((3*FA_QT + 2*FA_VT)*2)   // 90112 B

__global__ void __launch_bounds__(256) flash_attn(
    const half* __restrict__ qh, const half* __restrict__ kh,
    const half* __restrict__ vth, half* __restrict__ atth)
{
    extern __shared__ half sm[];
    uint32_t smBase = smem_u32(sm);
    int tid = threadIdx.x, lane = tid & 31, wid = tid >> 5;

    int bh = blockIdx.y;
    int b = bh >> 4, h = bh & 15;
    int q0 = blockIdx.x * 128;
    int qg0 = b * Ntok + q0;
    int kg0 = b * Ntok;
    int hcol = h * 64;
    size_t vbase = (size_t)bh * 64 * Ntok;

    auto ldQ = [&]() {
        #pragma unroll
        for (int i = 0; i < 4; i++) {
            int seg = tid + (i << 8);
            int row = seg >> 3;
            int cs = (seg & 7) << 3;
            const half* src = qh + (size_t)(qg0 + row) * Ii + hcol + cs;
            uint32_t dst = smBase + (uint32_t)((row * FA_PITCH + cs) * 2);
            CP_ASYNC16(dst, src);
        }
    };
    auto ldKV = [&](int chunk, int s) {
        int key0 = chunk << 7;
        #pragma unroll
        for (int i = 0; i < 8; i++) {
            int seg = tid + (i << 8);
            int t = seg >> 10;
            int w = seg & 1023;
            if (t == 0) {
                int row = w >> 3;
                int cs = (w & 7) << 3;
                const half* src = kh + (size_t)(kg0 + key0 + row) * Ii + hcol + cs;
                uint32_t dst = smBase + (uint32_t)((FA_KBASE + s * FA_QT + row * FA_PITCH + cs) * 2);
                CP_ASYNC16(dst, src);
            } else {
                int row = w >> 4;
                int cs = (w & 15) << 3;
                const half* src = vth + vbase + (size_t)row * Ntok + key0 + cs;
                uint32_t dst = smBase + (uint32_t)((FA_VBASE + s * FA_VT + row * FA_VPITCH + cs) * 2);
                CP_ASYNC16(dst, src);
            }
        }
    };

    int aRow = (lane & 7) + ((lane >> 3) & 1) * 8;
    int aCg  = (lane >> 4) * 8;
    int bRow = (lane & 7) + (lane >> 4) * 8;
    int bCg  = ((lane >> 3) & 1) * 8;

    float O[8][4];
    #pragma unroll
    for (int i = 0; i < 8; i++)
        #pragma unroll
        for (int e = 0; e < 4; e++) O[i][e] = 0.f;
    float M0 = -1e30f, M1 = -1e30f, L0 = 0.f, L1 = 0.f;

    ldQ(); ldKV(0, 0);
    CP_COMMIT();
    ldKV(1, 1);
    CP_COMMIT();

    for (int c = 0; c < 16; c++) {
        if (c < 15) asm volatile("cp.async.wait_group 1;" ::: "memory");
        else        asm volatile("cp.async.wait_group 0;" ::: "memory");
        __syncthreads();

        int s = c & 1;
        float S[16][4];
        #pragma unroll
        for (int i = 0; i < 16; i++)
            #pragma unroll
            for (int e = 0; e < 4; e++) S[i][e] = 0.f;

        uint32_t kTile = smBase + (uint32_t)((FA_KBASE + s * FA_QT) * 2);
        #pragma unroll
        for (int ks = 0; ks < 4; ks++) {
            uint32_t aH[4];
            uint32_t addrA = smBase + (uint32_t)(((wid * 16 + aRow) * FA_PITCH + ks * 16 + aCg) * 2);
            LDSM4(aH[0], aH[1], aH[2], aH[3], addrA);
            #pragma unroll
            for (int nn = 0; nn < 8; nn++) {
                uint32_t addrB = kTile + (uint32_t)(((nn * 16 + bRow) * FA_PITCH + ks * 16 + bCg) * 2);
                uint32_t bH[4];
                LDSM4(bH[0], bH[1], bH[2], bH[3], addrB);
                MMA16816(S[2 * nn],     aH, bH[0], bH[1]);
                MMA16816(S[2 * nn + 1], aH, bH[2], bH[3]);
            }
        }

        float cm0 = -1e30f, cm1 = -1e30f;
        #pragma unroll
        for (int i = 0; i < 16; i++) {
            cm0 = fmaxf(cm0, fmaxf(S[i][0], S[i][1]));
            cm1 = fmaxf(cm1, fmaxf(S[i][2], S[i][3]));
        }
        #pragma unroll
        for (int o = 1; o <= 2; o <<= 1) {
            cm0 = fmaxf(cm0, __shfl_xor_sync(0xffffffffu, cm0, o));
            cm1 = fmaxf(cm1, __shfl_xor_sync(0xffffffffu, cm1, o));
        }
        float nM0 = fmaxf(M0, cm0), nM1 = fmaxf(M1, cm1);
        float f0 = __expf(M0 - nM0), f1 = __expf(M1 - nM1);
        M0 = nM0; M1 = nM1;
        #pragma unroll
        for (int i = 0; i < 8; i++) {
            O[i][0] *= f0; O[i][1] *= f0; O[i][2] *= f1; O[i][3] *= f1;
        }
        float l0 = 0.f, l1 = 0.f;
        #pragma unroll
        for (int i = 0; i < 16; i++) {
            S[i][0] = __expf(S[i][0] - nM0);
            S[i][1] = __expf(S[i][1] - nM0);
            S[i][2] = __expf(S[i][2] - nM1);
            S[i][3] = __expf(S[i][3] - nM1);
            l0 += S[i][0] + S[i][1];
            l1 += S[i][2] + S[i][3];
        }
        #pragma unroll
        for (int o = 1; o <= 2; o <<= 1) {
            l0 += __shfl_xor_sync(0xffffffffu, l0, o);
            l1 += __shfl_xor_sync(0xffffffffu, l1, o);
        }
        L0 = L0 * f0 + l0;
        L1 = L1 * f1 + l1;

        uint32_t vTile = smBase + (uint32_t)((FA_VBASE + s * FA_VT) * 2);
        #pragma unroll
        for (int kk = 0; kk < 8; kk++) {
            uint32_t PhF[4];
            #pragma unroll
            for (int u = 0; u < 2; u++) {
                int t = 2 * kk + u;
                half2 h01 = __floats2half2_rn(S[t][0], S[t][1]);
                half2 h23 = __floats2half2_rn(S[t][2], S[t][3]);
                PhF[2 * u]     = *reinterpret_cast<uint32_t*>(&h01);
                PhF[2 * u + 1] = *reinterpret_cast<uint32_t*>(&h23);
            }
            #pragma unroll
            for (int nn = 0; nn < 4; nn++) {
                uint32_t addrV = vTile + (uint32_t)(((nn * 16 + bRow) * FA_VPITCH + kk * 16 + bCg) * 2);
                uint32_t vH[4];
                LDSM4(vH[0], vH[1], vH[2], vH[3], addrV);
                MMA16816(O[2 * nn],     PhF, vH[0], vH[1]);
                MMA16816(O[2 * nn + 1], PhF, vH[2], vH[3]);
            }
        }

        __syncthreads();
        if (c + 2 < 16) { ldKV(c + 2, s); CP_COMMIT(); }
    }

    float inv0 = 1.f / L0, inv1 = 1.f / L1;
    int r0 = qg0 + wid * 16 + (lane >> 2);
    int r1 = r0 + 8;
    #pragma unroll
    for (int nf = 0; nf < 8; nf++) {
        int d0 = nf * 8 + (lane & 3) * 2;
        *reinterpret_cast<half2*>(atth + (size_t)r0 * Ii + hcol + d0) =
            __floats2half2_rn(O[nf][0] * inv0, O[nf][1] * inv0);
        *reinterpret_cast<half2*>(atth + (size_t)r1 * Ii + hcol + d0) =
            __floats2half2_rn(O[nf][2] * inv1, O[nf][3] * inv1);
    }
}

// ---------------------------------------------------------------------------
// LayerNorm -> fp16 (single-pass, warp-shuffle, one barrier)
// ---------------------------------------------------------------------------
__global__ __launch_bounds__(256) void ln_kernel(
    const float* __restrict__ x, const float* __restrict__ g, const float* __restrict__ b,
    half* __restrict__ oh)
{
    size_t row = blockIdx.x;
    const float* xr = x + row * Dm;
    __shared__ float ws[8], ws2[8];
    int t = threadIdx.x, lane = t & 31, wid = t >> 5;
    float v[4];
    float s = 0.f, s2 = 0.f;
    #pragma unroll
    for (int j = 0; j < 4; j++) {
        v[j] = xr[t + j * 256];
        s += v[j];
        s2 += v[j] * v[j];
    }
    #pragma unroll
    for (int o = 16; o > 0; o >>= 1) {
        s  += __shfl_xor_sync(0xffffffffu, s,  o);
        s2 += __shfl_xor_sync(0xffffffffu, s2, o);
    }
    if (lane == 0) { ws[wid] = s; ws2[wid] = s2; }
    __syncthreads();
    float ts = 0.f, ts2 = 0.f;
    #pragma unroll
    for (int w = 0; w < 8; w++) { ts += ws[w]; ts2 += ws2[w]; }
    float mean = ts * (1.f / Dm);
    float var  = ts2 * (1.f / Dm) - mean * mean;
    float inv = rsqrtf(var + 1e-5f);
    #pragma unroll
    for (int j = 0; j < 4; j++) {
        int i = t + j * 256;
        oh[row * Dm + i] = __float2half_rn((v[j] - mean) * inv * g[i] + b[i]);
    }
}

// ---------------------------------------------------------------------------
// Softmax -> split fp16 (cross-attn)
// ---------------------------------------------------------------------------
__global__ __launch_bounds__(256) void softmax_split_kernel(
    const float* __restrict__ s, half* __restrict__ ph, half* __restrict__ pl,
    int cols, int ldin, int ldout)
{
    size_t row = blockIdx.x;
    const float* r = s + row * (size_t)ldin;
    __shared__ float red[256];
    int t = threadIdx.x;
    float v = (t < cols) ? r[t] : -INFINITY;
    red[t] = v; __syncthreads();
    for (int o = 128; o > 0; o >>= 1) { if (t < o) red[t] = fmaxf(red[t], red[t + o]); __syncthreads(); }
    float m = red[0]; __syncthreads();
    float e = (t < cols) ? __expf(v - m) : 0.f;
    red[t] = e; __syncthreads();
    for (int o = 128; o > 0; o >>= 1) { if (t < o) red[t] += red[t + o]; __syncthreads(); }
    float inv = 1.f / red[0];
    if (t < ldout) {
        half h, l; split2(e * inv, h, l);
        ph[row * (size_t)ldout + t] = h;
        pl[row * (size_t)ldout + t] = l;
    }
}

// ---------------------------------------------------------------------------
// Plain fp32 -> fp16
// ---------------------------------------------------------------------------
__global__ __launch_bounds__(256) void tohalf_kernel(
    const float* __restrict__ src, half* __restrict__ dh, long long n)
{
    long long i = (long long)blockIdx.x * 256 + threadIdx.x;
    if (i >= n) return;
    dh[i] = __float2half_rn(src[i]);
}

// ---------------------------------------------------------------------------
// Unified fast weight transpose (unchanged)
// ---------------------------------------------------------------------------
#define NSEG 10
struct TransDesc {
    const float* src[NSEG];
    half*        dst[NSEG];
    int R[NSEG], C[NSEG], start[NSEG], inter[NSEG];
};

__global__ __launch_bounds__(256) void multi_transpose(TransDesc d)
{
    __shared__ float tile[64][65];
    int bid = blockIdx.x;
    int s = 0;
    #pragma unroll
    for (int i = 1; i < NSEG; i++) if (bid >= d.start[i]) s = i;
    int local = bid - d.start[s];
    int R = d.R[s], C = d.C[s];
    int Rb = R >> 6;
    int r0 = (local % Rb) << 6;
    int c0 = (local / Rb) << 6;
    const float* src = d.src[s];
    half* dst = d.dst[s];
    int t = threadIdx.x;

    #pragma unroll
    for (int i = 0; i < 4; i++) {
        int idx = t + (i << 8);
        int row = idx >> 4;
        int col = (idx & 15) << 2;
        float4 v = *reinterpret_cast<const float4*>(src + (size_t)(r0 + row) * C + c0 + col);
        tile[row][col] = v.x; tile[row][col + 1] = v.y;
        tile[row][col + 2] = v.z; tile[row][col + 3] = v.w;
    }
    __syncthreads();

    bool inter = d.inter[s] != 0;
    #pragma unroll
    for (int i = 0; i < 4; i++) {
        int idx = t + (i << 8);
        int ccL = idx >> 4;
        int rr  = (idx & 15) << 2;
        int cc  = c0 + ccL;
        half hv[4];
        #pragma unroll
        for (int j = 0; j < 4; j++) hv[j] = __float2half_rn(tile[rr + j][ccL]);
        size_t orow = inter ? ((cc < FFd) ? (size_t)(2 * cc) : (size_t)(2 * (cc - FFd) + 1))
                            : (size_t)cc;
        *reinterpret_cast<uint2*>(dst + orow * R + r0 + rr) = *reinterpret_cast<uint2*>(hv);
    }
}

// ---------------------------------------------------------------------------
// Per-head V transpose, 64x64 vectorized (unchanged)
// ---------------------------------------------------------------------------
__global__ __launch_bounds__(256) void head_t64_kernel(
    const float* __restrict__ src, half* __restrict__ dst, int T, int Tpad)
{
    __shared__ float tile[64][65];
    int zh = blockIdx.z;
    int b = zh >> 4, h = zh & 15;
    int t0 = blockIdx.x * 64;
    int t = threadIdx.x;

    #pragma unroll
    for (int i = 0; i < 4; i++) {
        int idx = t + (i << 8);
        int row = idx >> 4;
        int col = (idx & 15) << 2;
        int tok = t0 + row;
        float4 v = make_float4(0.f, 0.f, 0.f, 0.f);
        if (tok < T)
            v = *reinterpret_cast<const float4*>(src + ((size_t)b * T + tok) * 1024 + h * 64 + col);
        tile[row][col] = v.x; tile[row][col + 1] = v.y;
        tile[row][col + 2] = v.z; tile[row][col + 3] = v.w;
    }
    __syncthreads();

    size_t base = (size_t)zh * 64 * Tpad;
    #pragma unroll
    for (int i = 0; i < 4; i++) {
        int idx = t + (i << 8);
        int dL = idx >> 4;
        int tt = (idx & 15) << 2;
        int tok = t0 + tt;
        if (tok + 3 < Tpad) {
            half hv[4];
            #pragma unroll
            for (int j = 0; j < 4; j++) hv[j] = __float2half_rn(tile[tt + j][dL]);
            *reinterpret_cast<uint2*>(dst + base + (size_t)dL * Tpad + tok) = *reinterpret_cast<uint2*>(hv);
        } else if (tok < Tpad) {
            for (int j = 0; j < 4 && tok + j < Tpad; j++)
                dst[base + (size_t)dL * Tpad + tok + j] = __float2half_rn(tile[tt + j][dL]);
        }
    }
}

// ---------------------------------------------------------------------------
// Orchestration
// ---------------------------------------------------------------------------
static inline dim3 ggrid(int M, int N, int z) { return dim3((N + 127) / 128, (M + 127) / 128, z); }

#define SYM(p, s) cudaGetSymbolAddress((void**)&p, s)

extern "C" void kernel_launch(void* const* d_in, const int* in_sizes, int n_in,
                              void* d_out, int out_size)
{
    const float* x     = (const float*)d_in[0];
    const float* ctx   = (const float*)d_in[1];
    const float* ln1_g = (const float*)d_in[2];
    const float* ln1_b = (const float*)d_in[3];
    const float* ln2_g = (const float*)d_in[4];
    const float* ln2_b = (const float*)d_in[5];
    const float* ln3_g = (const float*)d_in[6];
    const float* ln3_b = (const float*)d_in[7];
    const float* Wq1   = (const float*)d_in[8];
    const float* Wk1   = (const float*)d_in[9];
    const float* Wv1   = (const float*)d_in[10];
    const float* Wo1   = (const float*)d_in[11];
    const float* bo1   = (const float*)d_in[12];
    const float* Wq2   = (const float*)d_in[13];
    const float* Wk2   = (const float*)d_in[14];
    const float* Wv2   = (const float*)d_in[15];
    const float* Wo2   = (const float*)d_in[16];
    const float* bo2   = (const float*)d_in[17];
    const float* Wff1  = (const float*)d_in[18];
    const float* bff1  = (const float*)d_in[19];
    const float* Wff2  = (const float*)d_in[20];
    const float* bff2  = (const float*)d_in[21];
    float* out = (float*)d_out;

    half *lnh,*qh,*kh,*vth,*Ph,*Pl,*atth,*ctxh,*ffh;
    half *wqkv1,*wo1h,*wq2h,*wkv2,*wo2h,*wf1h,*wf2h;
    float *v,*sim,*x1,*x2;
    SYM(lnh,g_lnh); SYM(qh,g_qh); SYM(kh,g_kh);
    SYM(v,g_v); SYM(vth,g_vth); SYM(sim,g_sim); SYM(Ph,g_Ph); SYM(Pl,g_Pl);
    SYM(atth,g_atth); SYM(x1,g_x1); SYM(x2,g_x2);
    SYM(ctxh,g_ctxh); SYM(ffh,g_ffh);
    SYM(wqkv1,g_wqkv1); SYM(wo1h,g_wo1h); SYM(wq2h,g_wq2h); SYM(wkv2,g_wkv2);
    SYM(wo2h,g_wo2h); SYM(wf1h,g_wf1h); SYM(wf2h,g_wf2h);

    cudaFuncSetAttribute((const void*)mma_gemm<0,0,64>, cudaFuncAttributeMaxDynamicSharedMemorySize, SMEM_BK64);
    cudaFuncSetAttribute((const void*)mma_gemm<0,1,64>, cudaFuncAttributeMaxDynamicSharedMemorySize, SMEM_BK64);
    cudaFuncSetAttribute((const void*)mma_gemm<0,2,64>, cudaFuncAttributeMaxDynamicSharedMemorySize, SMEM_BK64);
    cudaFuncSetAttribute((const void*)mma_gemm<0,3,64>, cudaFuncAttributeMaxDynamicSharedMemorySize, SMEM_BK64);
    cudaFuncSetAttribute((const void*)mma_gemm<1,0,32>, cudaFuncAttributeMaxDynamicSharedMemorySize, SMEM_BK32S);
    cudaFuncSetAttribute((const void*)flash_attn, cudaFuncAttributeMaxDynamicSharedMemorySize, FA_SMEM_BYTES);

    // ---- single fused weight-transpose launch ----
    TransDesc td;
    int pos = 0, si = 0;
    auto addSeg = [&](const float* s, half* dd, int R, int C, int inter) {
        td.src[si] = s; td.dst[si] = dd; td.R[si] = R; td.C[si] = C;
        td.start[si] = pos; td.inter[si] = inter;
        pos += (R >> 6) * (C >> 6);
        si++;
    };
    addSeg(Wq1,  wqkv1,                    Dm,  Ii,     0);
    addSeg(Wk1,  wqkv1 + (size_t)Ii*Dm,   Dm,  Ii,     0);
    addSeg(Wv1,  wqkv1 + (size_t)2*Ii*Dm, Dm,  Ii,     0);
    addSeg(Wo1,  wo1h,                     Ii,  Dm,     0);
    addSeg(Wq2,  wq2h,                     Dm,  Ii,     0);
    addSeg(Wk2,  wkv2,                     DCc, Ii,     0);
    addSeg(Wv2,  wkv2 + (size_t)Ii*DCc,   DCc, Ii,     0);
    addSeg(Wo2,  wo2h,                     Ii,  Dm,     0);
    addSeg(Wff2, wf2h,                     FFd, Dm,     0);
    addSeg(Wff1, wf1h,                     Dm,  2*FFd,  1);
    multi_transpose<<<pos, 256>>>(td);
    tohalf_kernel<<<(BM2*DCc + 255)/256, 256>>>(ctx, ctxh, (long long)BM2*DCc);

    // ================= block 1: self-attention =================
    ln_kernel<<<BN, 256>>>(x, ln1_g, ln1_b, lnh);

    mma_gemm<0,2,64><<<ggrid(BN, 3*Ii, 1), 256, SMEM_BK64>>>(lnh, nullptr, wqkv1, nullptr, nullptr,
        v, qh, kh, BN, 3*Ii, Dm, Dm, Dm, Ii, 0,0,0,0,0,0, 1, SCALE);

    head_t64_kernel<<<dim3(Ntok/64, 1, BHh), 256>>>(v, vth, Ntok, Ntok);

    flash_attn<<<dim3(Ntok/128, BHh), 256, FA_SMEM_BYTES>>>(qh, kh, vth, atth);

    mma_gemm<0,0,64><<<ggrid(BN, Dm, 1), 256, SMEM_BK64>>>(atth, nullptr, wo1h, bo1, x,
        x1, nullptr, nullptr, BN, Dm, Ii, Ii, Ii, Dm, 0,0,0,0,0,0, 1, 1.f);

    // ================= block 2: cross-attention =================
    ln_kernel<<<BN, 256>>>(x1, ln2_g, ln2_b, lnh);

    mma_gemm<0,0,64><<<ggrid(BN, Ii, 1), 256, SMEM_BK64>>>(lnh, nullptr, wq2h, nullptr, nullptr,
        nullptr, qh, nullptr, BN, Ii, Dm, Dm, Dm, Ii, 0,0,0,0,0,0, 1, SCALE);

    mma_gemm<0,3,64><<<ggrid(BM2, 2*Ii, 1), 256, SMEM_BK64>>>(ctxh, nullptr, wkv2, nullptr, nullptr,
        v, kh, nullptr, BM2, 2*Ii, DCc, DCc, DCc, Ii, 0,0,0,0,0,0, 1, 1.f);

    head_t64_kernel<<<dim3((MctxP+63)/64, 1, BHh), 256>>>(v, vth, Mctx, MctxP);

    mma_gemm<0,0,64><<<ggrid(Ntok, Mctx, BHh), 256, SMEM_BK64>>>(qh, nullptr, kh, nullptr, nullptr,
        sim, nullptr, nullptr, Ntok, Mctx, DHd, Ii, Ii, MctxP,
        (long long)Ntok*Ii, 64, (long long)Mctx*Ii, 64,
        (long long)Hh*Ntok*MctxP, (long long)Ntok*MctxP, Hh, 1.f);

    softmax_split_kernel<<<BHh*Ntok, 256>>>(sim, Ph, Pl, Mctx, MctxP, MctxP);

    mma_gemm<1,0,32><<<ggrid(Ntok, DHd, BHh), 256, SMEM_BK32S>>>(Ph, Pl, vth, nullptr, nullptr,
        nullptr, atth, nullptr, Ntok, DHd, MctxP, MctxP, MctxP, Ii,
        (long long)Hh*Ntok*MctxP, (long long)Ntok*MctxP,
        (long long)Hh*DHd*MctxP, (long long)DHd*MctxP,
        (long long)Ntok*Ii, 64, Hh, 1.f);

    mma_gemm<0,0,64><<<ggrid(BN, Dm, 1), 256, SMEM_BK64>>>(atth, nullptr, wo2h, bo2, x1,
        x2, nullptr, nullptr, BN, Dm, Ii, Ii, Ii, Dm, 0,0,0,0,0,0, 1, 1.f);

    // ================= block 3: GEGLU FF =================
    ln_kernel<<<BN, 256>>>(x2, ln3_g, ln3_b, lnh);

    mma_gemm<0,1,64><<<ggrid(BN, 2*FFd, 1), 256, SMEM_BK64>>>(lnh, nullptr, wf1h, bff1, nullptr,
        nullptr, ffh, nullptr, BN, 2*FFd, Dm, Dm, Dm, FFd, 0,0,0,0,0,0, 1, 1.f);

    mma_gemm<0,0,64><<<ggrid(BN, Dm, 1), 256, SMEM_BK64>>>(ffh, nullptr, wf2h, bff2, x2,
        out, nullptr, nullptr, BN, Dm, FFd, FFd, FFd, Dm, 0,0,0,0,0,0, 1, 1.f);
}

// round 16
// speedup vs baseline: 1.5338x; 1.0017x over previous
#include <cuda_runtime.h>
#include <cuda_fp16.h>
#include <math.h>
#include <stdint.h>

// ---------------------------------------------------------------------------
// Problem constants
// ---------------------------------------------------------------------------
#define Bsz   2
#define Ntok  2048
#define Dm    1024
#define Hh    16
#define DHd   64
#define Ii    1024
#define DCc   768
#define Mctx  77
#define MctxP 80
#define FFd   4096
#define BN    (Bsz*Ntok)
#define BM2   (Bsz*Mctx)
#define BHh   (Bsz*Hh)
#define SCALE 0.125f

// ---------------------------------------------------------------------------
// Device scratch
// ---------------------------------------------------------------------------
#define DEVARR(name, type, count) __device__ __align__(16) type name[(size_t)(count)]

DEVARR(g_lnh,  half, BN*Dm);
DEVARR(g_qh,   half, BN*Ii);
DEVARR(g_kh,   half, BN*Ii);
DEVARR(g_v,    float, BN*Ii);
DEVARR(g_vth,  half, BHh*DHd*Ntok);
DEVARR(g_sim,  float, (size_t)BHh*Ntok*MctxP);
DEVARR(g_Ph,   half, (size_t)BHh*Ntok*MctxP); DEVARR(g_Pl, half, (size_t)BHh*Ntok*MctxP);
DEVARR(g_atth, half, BN*Ii);
DEVARR(g_x1,   float, BN*Dm);  DEVARR(g_x2,   float, BN*Dm);
DEVARR(g_ctxh, half, BM2*DCc);
DEVARR(g_ffh,  half, (size_t)BN*FFd);
// transposed weights [N x K], hi only
DEVARR(g_wqkv1, half, (size_t)3*Dm*Ii);
DEVARR(g_wo1h,  half, Dm*Ii);
DEVARR(g_wq2h,  half, Dm*Ii);
DEVARR(g_wkv2,  half, (size_t)2*Ii*DCc);
DEVARR(g_wo2h,  half, Dm*Ii);
DEVARR(g_wf1h,  half, (size_t)Dm*2*FFd);   // interleaved: row 2j=h, 2j+1=gate
DEVARR(g_wf2h,  half, (size_t)FFd*Dm);

// ---------------------------------------------------------------------------
// Helpers
// ---------------------------------------------------------------------------
__device__ __forceinline__ uint32_t smem_u32(const void* p) {
    uint32_t a;
    asm("{ .reg .u64 t; cvta.to.shared.u64 t, %1; cvt.u32.u64 %0, t; }" : "=r"(a) : "l"(p));
    return a;
}
__device__ __forceinline__ void split2(float x, half& h, half& l) {
    h = __float2half_rn(x);
    l = __float2half_rn(x - __half2float(h));
}
__device__ __forceinline__ float gelu_exact(float g) {
    return 0.5f * g * (1.f + erff(g * 0.70710678118654752440f));
}

#define LDSM4(r0, r1, r2, r3, addr) \
    asm volatile("ldmatrix.sync.aligned.m8n8.x4.shared.b16 {%0,%1,%2,%3}, [%4];" \
        : "=r"(r0), "=r"(r1), "=r"(r2), "=r"(r3) : "r"(addr))

#define MMA16816(c, a, b0, b1) \
    asm volatile("mma.sync.aligned.m16n8k16.row.col.f32.f16.f16.f32 " \
        "{%0,%1,%2,%3}, {%4,%5,%6,%7}, {%8,%9}, {%0,%1,%2,%3};" \
        : "+f"((c)[0]), "+f"((c)[1]), "+f"((c)[2]), "+f"((c)[3]) \
        : "r"((a)[0]), "r"((a)[1]), "r"((a)[2]), "r"((a)[3]), "r"(b0), "r"(b1))

#define CP_ASYNC16(dst, src) \
    asm volatile("cp.async.cg.shared.global [%0], [%1], 16;" :: "r"(dst), "l"(src) : "memory")
#define CP_COMMIT() asm volatile("cp.async.commit_group;" ::: "memory")

// ---------------------------------------------------------------------------
// mma.sync GEMM: acc = A @ Bh^T, 128x128 tile, 8 warps.
// 3-buffer rotation, depth-1 prefetch, ONE __syncthreads per stage.
// MODE 0: C/Ch = alpha*acc (+bias)(+resid); 1: GEGLU; 2: QKV route; 3: KV route
// ---------------------------------------------------------------------------
template<int SPLIT_A, int MODE, int BK>
__global__ void __launch_bounds__(256, 2) mma_gemm(
    const half* __restrict__ Ah_, const half* __restrict__ Al_,
    const half* __restrict__ Bh_,
    const float* __restrict__ bias, const float* __restrict__ resid,
    float* __restrict__ C, half* __restrict__ Ch, half* __restrict__ Ch2,
    int M, int N, int K, int lda, int ldb, int ldc,
    long long aO, long long aI, long long bO, long long bI,
    long long cO, long long cI, int nInner, float alpha)
{
    constexpr int NT  = 2 + SPLIT_A;
    constexpr int PK  = BK + 8;
    constexpr int TH  = 128 * PK;
    constexpr int SPT = 128 * (BK / 8);
    constexpr int ITR = NT * SPT / 256;

    extern __shared__ half sm[];
    uint32_t smBase = smem_u32(sm);
    int tid = threadIdx.x, lane = tid & 31, wid = tid >> 5;
    int warpM = wid >> 1, warpN = wid & 1;

    int z = blockIdx.z, zo = z / nInner, zi = z % nInner;
    const half* Ahp = Ah_ + (long long)zo * aO + (long long)zi * aI;
    const half* Alp = SPLIT_A ? (Al_ + (long long)zo * aO + (long long)zi * aI) : nullptr;
    const half* Bhp = Bh_ + (long long)zo * bO + (long long)zi * bI;
    long long offC = (long long)zo * cO + (long long)zi * cI;

    int rowBase = blockIdx.y * 128, colBase = blockIdx.x * 128;

    float acc[2][8][4];
    #pragma unroll
    for (int i = 0; i < 2; i++)
        #pragma unroll
        for (int j = 0; j < 8; j++)
            #pragma unroll
            for (int e = 0; e < 4; e++) acc[i][j][e] = 0.f;

    int nc = (K + BK - 1) / BK;

    auto load_stage = [&](int c, int s) {
        int k0 = c * BK;
        #pragma unroll
        for (int i = 0; i < ITR; i++) {
            int seg  = tid + (i << 8);
            int tile = seg / SPT;
            int w    = seg % SPT;
            int row  = w / (BK / 8);
            int cs   = (w % (BK / 8)) << 3;
            bool isA = tile < (NT - 1);
            const half* base = (tile == 0) ? Ahp : (SPLIT_A && tile == 1) ? Alp : Bhp;
            int ld  = isA ? lda : ldb;
            int gr  = (isA ? rowBase : colBase) + row;
            int gk  = k0 + cs;
            bool ok = (gr < (isA ? M : N)) && (gk + 8 <= K);
            const half* src = ok ? (base + (size_t)gr * ld + gk) : base;
            uint32_t dst = smBase + (uint32_t)(((s * NT + tile) * TH + row * PK + cs) * 2);
            uint32_t sz = ok ? 16u : 0u;
            asm volatile("cp.async.cg.shared.global [%0], [%1], 16, %2;"
                         :: "r"(dst), "l"(src), "r"(sz) : "memory");
        }
    };

    int aRow = (lane & 7) + ((lane >> 3) & 1) * 8;
    int aCg  = (lane >> 4) * 8;
    int bRow = (lane & 7) + (lane >> 4) * 8;
    int bCg  = ((lane >> 3) & 1) * 8;

    auto compute_stage = [&](int s) {
        uint32_t sBase = smBase + (uint32_t)(s * NT * TH * 2);
        #pragma unroll
        for (int ks = 0; ks < BK / 16; ks++) {
            uint32_t ah[2][4], al[2][4];
            #pragma unroll
            for (int mm = 0; mm < 2; mm++) {
                uint32_t addr = sBase + (uint32_t)(((warpM * 32 + mm * 16 + aRow) * PK + ks * 16 + aCg) * 2);
                LDSM4(ah[mm][0], ah[mm][1], ah[mm][2], ah[mm][3], addr);
                if (SPLIT_A) LDSM4(al[mm][0], al[mm][1], al[mm][2], al[mm][3], addr + TH * 2);
            }
            #pragma unroll
            for (int nn = 0; nn < 4; nn++) {
                uint32_t baddr = sBase + (uint32_t)(((NT - 1) * TH + (warpN * 64 + nn * 16 + bRow) * PK + ks * 16 + bCg) * 2);
                uint32_t bh[4];
                LDSM4(bh[0], bh[1], bh[2], bh[3], baddr);
                #pragma unroll
                for (int mm = 0; mm < 2; mm++) {
                    MMA16816(acc[mm][2 * nn],     ah[mm], bh[0], bh[1]);
                    MMA16816(acc[mm][2 * nn + 1], ah[mm], bh[2], bh[3]);
                    if (SPLIT_A) {
                        MMA16816(acc[mm][2 * nn],     al[mm], bh[0], bh[1]);
                        MMA16816(acc[mm][2 * nn + 1], al[mm], bh[2], bh[3]);
                    }
                }
            }
        }
    };

    load_stage(0, 0);
    CP_COMMIT();
    int bufC = 0, bufL = 1;
    for (int c = 0; c < nc; c++) {
        if (c + 1 < nc) {
            load_stage(c + 1, bufL);
            CP_COMMIT();
            asm volatile("cp.async.wait_group 1;" ::: "memory");
        } else {
            asm volatile("cp.async.wait_group 0;" ::: "memory");
        }
        __syncthreads();
        compute_stage(bufC);
        bufC = (bufC == 2) ? 0 : bufC + 1;
        bufL = (bufL == 2) ? 0 : bufL + 1;
    }

    if (MODE == 1) {
        #pragma unroll
        for (int mm = 0; mm < 2; mm++) {
            #pragma unroll
            for (int nf = 0; nf < 8; nf++) {
                int rr = rowBase + warpM * 32 + mm * 16 + (lane >> 2);
                int gc = colBase + warpN * 64 + nf * 8 + (lane & 3) * 2;
                int j  = gc >> 1;
                float bh_ = bias[j], bg_ = bias[FFd + j];
                float h0 = acc[mm][nf][0] + bh_;
                float g0 = acc[mm][nf][1] + bg_;
                Ch[(size_t)rr * ldc + j] = __float2half_rn(h0 * gelu_exact(g0));
                float h1 = acc[mm][nf][2] + bh_;
                float g1 = acc[mm][nf][3] + bg_;
                Ch[(size_t)(rr + 8) * ldc + j] = __float2half_rn(h1 * gelu_exact(g1));
            }
        }
    } else if (MODE == 2 || MODE == 3) {
        #pragma unroll
        for (int mm = 0; mm < 2; mm++) {
            #pragma unroll
            for (int nf = 0; nf < 8; nf++) {
                int r  = rowBase + warpM * 32 + mm * 16 + (lane >> 2);
                int cc = colBase + warpN * 64 + nf * 8 + (lane & 3) * 2;
                #pragma unroll
                for (int e = 0; e < 4; e++) {
                    int rr = r + (e >> 1) * 8;
                    int gc = cc + (e & 1);
                    if (rr < M) {
                        float val = acc[mm][nf][e];
                        if (MODE == 2) {
                            if (gc < Ii)
                                Ch[(size_t)rr * Ii + gc] = __float2half_rn(val * alpha);
                            else if (gc < 2 * Ii)
                                Ch2[(size_t)rr * Ii + gc - Ii] = __float2half_rn(val);
                            else
                                C[(size_t)rr * Ii + gc - 2 * Ii] = val;
                        } else {
                            if (gc < Ii)
                                Ch[(size_t)rr * Ii + gc] = __float2half_rn(val);
                            else
                                C[(size_t)rr * Ii + gc - Ii] = val;
                        }
                    }
                }
            }
        }
    } else {
        // MODE 0: vectorized (float2/half2) with N edge guard
        #pragma unroll
        for (int mm = 0; mm < 2; mm++) {
            #pragma unroll
            for (int nf = 0; nf < 8; nf++) {
                int r  = rowBase + warpM * 32 + mm * 16 + (lane >> 2);
                int gc = colBase + warpN * 64 + nf * 8 + (lane & 3) * 2;
                #pragma unroll
                for (int p = 0; p < 2; p++) {
                    int rr = r + p * 8;
                    if (rr >= M) continue;
                    float v0 = acc[mm][nf][2 * p], v1 = acc[mm][nf][2 * p + 1];
                    size_t idx = (size_t)offC + (size_t)rr * ldc + gc;
                    if (gc + 1 < N) {
                        v0 *= alpha; v1 *= alpha;
                        if (bias) { v0 += bias[gc]; v1 += bias[gc + 1]; }
                        if (resid) {
                            float2 rv = *reinterpret_cast<const float2*>(resid + idx);
                            v0 += rv.x; v1 += rv.y;
                        }
                        if (C) *reinterpret_cast<float2*>(C + idx) = make_float2(v0, v1);
                        if (Ch) *reinterpret_cast<half2*>(Ch + idx) = __floats2half2_rn(v0, v1);
                    } else if (gc < N) {
                        v0 *= alpha;
                        if (bias) v0 += bias[gc];
                        if (resid) v0 += resid[idx];
                        if (C) C[idx] = v0;
                        if (Ch) Ch[idx] = __float2half_rn(v0);
                    }
                }
            }
        }
    }
}

#define SMEM_BK64  (3*2*(128*72)*2)   // 110592 B
#define SMEM_BK32S (3*3*(128*40)*2)   // 92160 B

// ---------------------------------------------------------------------------
// Fused flash self-attention (round-13 version, V [d][key] + plain ldsm).
// ---------------------------------------------------------------------------
#define FA_PITCH  72
#define FA_VPITCH 136
#define FA_QT     (128*FA_PITCH)
#define FA_VT     (64*FA_VPITCH)
#define FA_KBASE  (FA_QT)
#define FA_VBASE  (3*FA_QT)
#define FA_SMEM_BYTES ((3*FA_QT + 2*FA_VT)*2)   // 90112 B

__global__ void __launch_bounds__(256) flash_attn(
    const half* __restrict__ qh, const half* __restrict__ kh,
    const half* __restrict__ vth, half* __restrict__ atth)
{
    extern __shared__ half sm[];
    uint32_t smBase = smem_u32(sm);
    int tid = threadIdx.x, lane = tid & 31, wid = tid >> 5;

    int bh = blockIdx.y;
    int b = bh >> 4, h = bh & 15;
    int q0 = blockIdx.x * 128;
    int qg0 = b * Ntok + q0;
    int kg0 = b * Ntok;
    int hcol = h * 64;
    size_t vbase = (size_t)bh * 64 * Ntok;

    auto ldQ = [&]() {
        #pragma unroll
        for (int i = 0; i < 4; i++) {
            int seg = tid + (i << 8);
            int row = seg >> 3;
            int cs = (seg & 7) << 3;
            const half* src = qh + (size_t)(qg0 + row) * Ii + hcol + cs;
            uint32_t dst = smBase + (uint32_t)((row * FA_PITCH + cs) * 2);
            CP_ASYNC16(dst, src);
        }
    };
    auto ldKV = [&](int chunk, int s) {
        int key0 = chunk << 7;
        #pragma unroll
        for (int i = 0; i < 8; i++) {
            int seg = tid + (i << 8);
            int t = seg >> 10;
            int w = seg & 1023;
            if (t == 0) {
                int row = w >> 3;
                int cs = (w & 7) << 3;
                const half* src = kh + (size_t)(kg0 + key0 + row) * Ii + hcol + cs;
                uint32_t dst = smBase + (uint32_t)((FA_KBASE + s * FA_QT + row * FA_PITCH + cs) * 2);
                CP_ASYNC16(dst, src);
            } else {
                int row = w >> 4;
                int cs = (w & 15) << 3;
                const half* src = vth + vbase + (size_t)row * Ntok + key0 + cs;
                uint32_t dst = smBase + (uint32_t)((FA_VBASE + s * FA_VT + row * FA_VPITCH + cs) * 2);
                CP_ASYNC16(dst, src);
            }
        }
    };

    int aRow = (lane & 7) + ((lane >> 3) & 1) * 8;
    int aCg  = (lane >> 4) * 8;
    int bRow = (lane & 7) + (lane >> 4) * 8;
    int bCg  = ((lane >> 3) & 1) * 8;

    float O[8][4];
    #pragma unroll
    for (int i = 0; i < 8; i++)
        #pragma unroll
        for (int e = 0; e < 4; e++) O[i][e] = 0.f;
    float M0 = -1e30f, M1 = -1e30f, L0 = 0.f, L1 = 0.f;

    ldQ(); ldKV(0, 0);
    CP_COMMIT();
    ldKV(1, 1);
    CP_COMMIT();

    for (int c = 0; c < 16; c++) {
        if (c < 15) asm volatile("cp.async.wait_group 1;" ::: "memory");
        else        asm volatile("cp.async.wait_group 0;" ::: "memory");
        __syncthreads();

        int s = c & 1;
        float S[16][4];
        #pragma unroll
        for (int i = 0; i < 16; i++)
            #pragma unroll
            for (int e = 0; e < 4; e++) S[i][e] = 0.f;

        uint32_t kTile = smBase + (uint32_t)((FA_KBASE + s * FA_QT) * 2);
        #pragma unroll
        for (int ks = 0; ks < 4; ks++) {
            uint32_t aH[4];
            uint32_t addrA = smBase + (uint32_t)(((wid * 16 + aRow) * FA_PITCH + ks * 16 + aCg) * 2);
            LDSM4(aH[0], aH[1], aH[2], aH[3], addrA);
            #pragma unroll
            for (int nn = 0; nn < 8; nn++) {
                uint32_t addrB = kTile + (uint32_t)(((nn * 16 + bRow) * FA_PITCH + ks * 16 + bCg) * 2);
                uint32_t bH[4];
                LDSM4(bH[0], bH[1], bH[2], bH[3], addrB);
                MMA16816(S[2 * nn],     aH, bH[0], bH[1]);
                MMA16816(S[2 * nn + 1], aH, bH[2], bH[3]);
            }
        }

        float cm0 = -1e30f, cm1 = -1e30f;
        #pragma unroll
        for (int i = 0; i < 16; i++) {
            cm0 = fmaxf(cm0, fmaxf(S[i][0], S[i][1]));
            cm1 = fmaxf(cm1, fmaxf(S[i][2], S[i][3]));
        }
        #pragma unroll
        for (int o = 1; o <= 2; o <<= 1) {
            cm0 = fmaxf(cm0, __shfl_xor_sync(0xffffffffu, cm0, o));
            cm1 = fmaxf(cm1, __shfl_xor_sync(0xffffffffu, cm1, o));
        }
        float nM0 = fmaxf(M0, cm0), nM1 = fmaxf(M1, cm1);
        float f0 = __expf(M0 - nM0), f1 = __expf(M1 - nM1);
        M0 = nM0; M1 = nM1;
        #pragma unroll
        for (int i = 0; i < 8; i++) {
            O[i][0] *= f0; O[i][1] *= f0; O[i][2] *= f1; O[i][3] *= f1;
        }
        float l0 = 0.f, l1 = 0.f;
        #pragma unroll
        for (int i = 0; i < 16; i++) {
            S[i][0] = __expf(S[i][0] - nM0);
            S[i][1] = __expf(S[i][1] - nM0);
            S[i][2] = __expf(S[i][2] - nM1);
            S[i][3] = __expf(S[i][3] - nM1);
            l0 += S[i][0] + S[i][1];
            l1 += S[i][2] + S[i][3];
        }
        #pragma unroll
        for (int o = 1; o <= 2; o <<= 1) {
            l0 += __shfl_xor_sync(0xffffffffu, l0, o);
            l1 += __shfl_xor_sync(0xffffffffu, l1, o);
        }
        L0 = L0 * f0 + l0;
        L1 = L1 * f1 + l1;

        uint32_t vTile = smBase + (uint32_t)((FA_VBASE + s * FA_VT) * 2);
        #pragma unroll
        for (int kk = 0; kk < 8; kk++) {
            uint32_t PhF[4];
            #pragma unroll
            for (int u = 0; u < 2; u++) {
                int t = 2 * kk + u;
                half2 h01 = __floats2half2_rn(S[t][0], S[t][1]);
                half2 h23 = __floats2half2_rn(S[t][2], S[t][3]);
                PhF[2 * u]     = *reinterpret_cast<uint32_t*>(&h01);
                PhF[2 * u + 1] = *reinterpret_cast<uint32_t*>(&h23);
            }
            #pragma unroll
            for (int nn = 0; nn < 4; nn++) {
                uint32_t addrV = vTile + (uint32_t)(((nn * 16 + bRow) * FA_VPITCH + kk * 16 + bCg) * 2);
                uint32_t vH[4];
                LDSM4(vH[0], vH[1], vH[2], vH[3], addrV);
                MMA16816(O[2 * nn],     PhF, vH[0], vH[1]);
                MMA16816(O[2 * nn + 1], PhF, vH[2], vH[3]);
            }
        }

        __syncthreads();
        if (c + 2 < 16) { ldKV(c + 2, s); CP_COMMIT(); }
    }

    float inv0 = 1.f / L0, inv1 = 1.f / L1;
    int r0 = qg0 + wid * 16 + (lane >> 2);
    int r1 = r0 + 8;
    #pragma unroll
    for (int nf = 0; nf < 8; nf++) {
        int d0 = nf * 8 + (lane & 3) * 2;
        *reinterpret_cast<half2*>(atth + (size_t)r0 * Ii + hcol + d0) =
            __floats2half2_rn(O[nf][0] * inv0, O[nf][1] * inv0);
        *reinterpret_cast<half2*>(atth + (size_t)r1 * Ii + hcol + d0) =
            __floats2half2_rn(O[nf][2] * inv1, O[nf][3] * inv1);
    }
}

// ---------------------------------------------------------------------------
// LayerNorm -> fp16 (single-pass, warp-shuffle, one barrier)
// ---------------------------------------------------------------------------
__global__ __launch_bounds__(256) void ln_kernel(
    const float* __restrict__ x, const float* __restrict__ g, const float* __restrict__ b,
    half* __restrict__ oh)
{
    size_t row = blockIdx.x;
    const float* xr = x + row * Dm;
    __shared__ float ws[8], ws2[8];
    int t = threadIdx.x, lane = t & 31, wid = t >> 5;
    float v[4];
    float s = 0.f, s2 = 0.f;
    #pragma unroll
    for (int j = 0; j < 4; j++) {
        v[j] = xr[t + j * 256];
        s += v[j];
        s2 += v[j] * v[j];
    }
    #pragma unroll
    for (int o = 16; o > 0; o >>= 1) {
        s  += __shfl_xor_sync(0xffffffffu, s,  o);
        s2 += __shfl_xor_sync(0xffffffffu, s2, o);
    }
    if (lane == 0) { ws[wid] = s; ws2[wid] = s2; }
    __syncthreads();
    float ts = 0.f, ts2 = 0.f;
    #pragma unroll
    for (int w = 0; w < 8; w++) { ts += ws[w]; ts2 += ws2[w]; }
    float mean = ts * (1.f / Dm);
    float var  = ts2 * (1.f / Dm) - mean * mean;
    float inv = rsqrtf(var + 1e-5f);
    #pragma unroll
    for (int j = 0; j < 4; j++) {
        int i = t + j * 256;
        oh[row * Dm + i] = __float2half_rn((v[j] - mean) * inv * g[i] + b[i]);
    }
}

// ---------------------------------------------------------------------------
// Softmax -> split fp16 (cross-attn)
// ---------------------------------------------------------------------------
__global__ __launch_bounds__(256) void softmax_split_kernel(
    const float* __restrict__ s, half* __restrict__ ph, half* __restrict__ pl,
    int cols, int ldin, int ldout)
{
    size_t row = blockIdx.x;
    const float* r = s + row * (size_t)ldin;
    __shared__ float red[256];
    int t = threadIdx.x;
    float v = (t < cols) ? r[t] : -INFINITY;
    red[t] = v; __syncthreads();
    for (int o = 128; o > 0; o >>= 1) { if (t < o) red[t] = fmaxf(red[t], red[t + o]); __syncthreads(); }
    float m = red[0]; __syncthreads();
    float e = (t < cols) ? __expf(v - m) : 0.f;
    red[t] = e; __syncthreads();
    for (int o = 128; o > 0; o >>= 1) { if (t < o) red[t] += red[t + o]; __syncthreads(); }
    float inv = 1.f / red[0];
    if (t < ldout) {
        half h, l; split2(e * inv, h, l);
        ph[row * (size_t)ldout + t] = h;
        pl[row * (size_t)ldout + t] = l;
    }
}

// ---------------------------------------------------------------------------
// Plain fp32 -> fp16
// ---------------------------------------------------------------------------
__global__ __launch_bounds__(256) void tohalf_kernel(
    const float* __restrict__ src, half* __restrict__ dh, long long n)
{
    long long i = (long long)blockIdx.x * 256 + threadIdx.x;
    if (i >= n) return;
    dh[i] = __float2half_rn(src[i]);
}

// ---------------------------------------------------------------------------
// Unified fast weight transpose (unchanged)
// ---------------------------------------------------------------------------
#define NSEG 10
struct TransDesc {
    const float* src[NSEG];
    half*        dst[NSEG];
    int R[NSEG], C[NSEG], start[NSEG], inter[NSEG];
};

__global__ __launch_bounds__(256) void multi_transpose(TransDesc d)
{
    __shared__ float tile[64][65];
    int bid = blockIdx.x;
    int s = 0;
    #pragma unroll
    for (int i = 1; i < NSEG; i++) if (bid >= d.start[i]) s = i;
    int local = bid - d.start[s];
    int R = d.R[s], C = d.C[s];
    int Rb = R >> 6;
    int r0 = (local % Rb) << 6;
    int c0 = (local / Rb) << 6;
    const float* src = d.src[s];
    half* dst = d.dst[s];
    int t = threadIdx.x;

    #pragma unroll
    for (int i = 0; i < 4; i++) {
        int idx = t + (i << 8);
        int row = idx >> 4;
        int col = (idx & 15) << 2;
        float4 v = *reinterpret_cast<const float4*>(src + (size_t)(r0 + row) * C + c0 + col);
        tile[row][col] = v.x; tile[row][col + 1] = v.y;
        tile[row][col + 2] = v.z; tile[row][col + 3] = v.w;
    }
    __syncthreads();

    bool inter = d.inter[s] != 0;
    #pragma unroll
    for (int i = 0; i < 4; i++) {
        int idx = t + (i << 8);
        int ccL = idx >> 4;
        int rr  = (idx & 15) << 2;
        int cc  = c0 + ccL;
        half hv[4];
        #pragma unroll
        for (int j = 0; j < 4; j++) hv[j] = __float2half_rn(tile[rr + j][ccL]);
        size_t orow = inter ? ((cc < FFd) ? (size_t)(2 * cc) : (size_t)(2 * (cc - FFd) + 1))
                            : (size_t)cc;
        *reinterpret_cast<uint2*>(dst + orow * R + r0 + rr) = *reinterpret_cast<uint2*>(hv);
    }
}

// ---------------------------------------------------------------------------
// Per-head V transpose, 64x64 vectorized (unchanged)
// ---------------------------------------------------------------------------
__global__ __launch_bounds__(256) void head_t64_kernel(
    const float* __restrict__ src, half* __restrict__ dst, int T, int Tpad)
{
    __shared__ float tile[64][65];
    int zh = blockIdx.z;
    int b = zh >> 4, h = zh & 15;
    int t0 = blockIdx.x * 64;
    int t = threadIdx.x;

    #pragma unroll
    for (int i = 0; i < 4; i++) {
        int idx = t + (i << 8);
        int row = idx >> 4;
        int col = (idx & 15) << 2;
        int tok = t0 + row;
        float4 v = make_float4(0.f, 0.f, 0.f, 0.f);
        if (tok < T)
            v = *reinterpret_cast<const float4*>(src + ((size_t)b * T + tok) * 1024 + h * 64 + col);
        tile[row][col] = v.x; tile[row][col + 1] = v.y;
        tile[row][col + 2] = v.z; tile[row][col + 3] = v.w;
    }
    __syncthreads();

    size_t base = (size_t)zh * 64 * Tpad;
    #pragma unroll
    for (int i = 0; i < 4; i++) {
        int idx = t + (i << 8);
        int dL = idx >> 4;
        int tt = (idx & 15) << 2;
        int tok = t0 + tt;
        if (tok + 3 < Tpad) {
            half hv[4];
            #pragma unroll
            for (int j = 0; j < 4; j++) hv[j] = __float2half_rn(tile[tt + j][dL]);
            *reinterpret_cast<uint2*>(dst + base + (size_t)dL * Tpad + tok) = *reinterpret_cast<uint2*>(hv);
        } else if (tok < Tpad) {
            for (int j = 0; j < 4 && tok + j < Tpad; j++)
                dst[base + (size_t)dL * Tpad + tok + j] = __float2half_rn(tile[tt + j][dL]);
        }
    }
}

// ---------------------------------------------------------------------------
// Orchestration
// ---------------------------------------------------------------------------
static inline dim3 ggrid(int M, int N, int z) { return dim3((N + 127) / 128, (M + 127) / 128, z); }

#define SYM(p, s) cudaGetSymbolAddress((void**)&p, s)

extern "C" void kernel_launch(void* const* d_in, const int* in_sizes, int n_in,
                              void* d_out, int out_size)
{
    const float* x     = (const float*)d_in[0];
    const float* ctx   = (const float*)d_in[1];
    const float* ln1_g = (const float*)d_in[2];
    const float* ln1_b = (const float*)d_in[3];
    const float* ln2_g = (const float*)d_in[4];
    const float* ln2_b = (const float*)d_in[5];
    const float* ln3_g = (const float*)d_in[6];
    const float* ln3_b = (const float*)d_in[7];
    const float* Wq1   = (const float*)d_in[8];
    const float* Wk1   = (const float*)d_in[9];
    const float* Wv1   = (const float*)d_in[10];
    const float* Wo1   = (const float*)d_in[11];
    const float* bo1   = (const float*)d_in[12];
    const float* Wq2   = (const float*)d_in[13];
    const float* Wk2   = (const float*)d_in[14];
    const float* Wv2   = (const float*)d_in[15];
    const float* Wo2   = (const float*)d_in[16];
    const float* bo2   = (const float*)d_in[17];
    const float* Wff1  = (const float*)d_in[18];
    const float* bff1  = (const float*)d_in[19];
    const float* Wff2  = (const float*)d_in[20];
    const float* bff2  = (const float*)d_in[21];
    float* out = (float*)d_out;

    half *lnh,*qh,*kh,*vth,*Ph,*Pl,*atth,*ctxh,*ffh;
    half *wqkv1,*wo1h,*wq2h,*wkv2,*wo2h,*wf1h,*wf2h;
    float *v,*sim,*x1,*x2;
    SYM(lnh,g_lnh); SYM(qh,g_qh); SYM(kh,g_kh);
    SYM(v,g_v); SYM(vth,g_vth); SYM(sim,g_sim); SYM(Ph,g_Ph); SYM(Pl,g_Pl);
    SYM(atth,g_atth); SYM(x1,g_x1); SYM(x2,g_x2);
    SYM(ctxh,g_ctxh); SYM(ffh,g_ffh);
    SYM(wqkv1,g_wqkv1); SYM(wo1h,g_wo1h); SYM(wq2h,g_wq2h); SYM(wkv2,g_wkv2);
    SYM(wo2h,g_wo2h); SYM(wf1h,g_wf1h); SYM(wf2h,g_wf2h);

    cudaFuncSetAttribute((const void*)mma_gemm<0,0,64>, cudaFuncAttributeMaxDynamicSharedMemorySize, SMEM_BK64);
    cudaFuncSetAttribute((const void*)mma_gemm<0,1,64>, cudaFuncAttributeMaxDynamicSharedMemorySize, SMEM_BK64);
    cudaFuncSetAttribute((const void*)mma_gemm<0,2,64>, cudaFuncAttributeMaxDynamicSharedMemorySize, SMEM_BK64);
    cudaFuncSetAttribute((const void*)mma_gemm<0,3,64>, cudaFuncAttributeMaxDynamicSharedMemorySize, SMEM_BK64);
    cudaFuncSetAttribute((const void*)mma_gemm<1,0,32>, cudaFuncAttributeMaxDynamicSharedMemorySize, SMEM_BK32S);
    cudaFuncSetAttribute((const void*)flash_attn, cudaFuncAttributeMaxDynamicSharedMemorySize, FA_SMEM_BYTES);

    // ---- single fused weight-transpose launch ----
    TransDesc td;
    int pos = 0, si = 0;
    auto addSeg = [&](const float* s, half* dd, int R, int C, int inter) {
        td.src[si] = s; td.dst[si] = dd; td.R[si] = R; td.C[si] = C;
        td.start[si] = pos; td.inter[si] = inter;
        pos += (R >> 6) * (C >> 6);
        si++;
    };
    addSeg(Wq1,  wqkv1,                    Dm,  Ii,     0);
    addSeg(Wk1,  wqkv1 + (size_t)Ii*Dm,   Dm,  Ii,     0);
    addSeg(Wv1,  wqkv1 + (size_t)2*Ii*Dm, Dm,  Ii,     0);
    addSeg(Wo1,  wo1h,                     Ii,  Dm,     0);
    addSeg(Wq2,  wq2h,                     Dm,  Ii,     0);
    addSeg(Wk2,  wkv2,                     DCc, Ii,     0);
    addSeg(Wv2,  wkv2 + (size_t)Ii*DCc,   DCc, Ii,     0);
    addSeg(Wo2,  wo2h,                     Ii,  Dm,     0);
    addSeg(Wff2, wf2h,                     FFd, Dm,     0);
    addSeg(Wff1, wf1h,                     Dm,  2*FFd,  1);
    multi_transpose<<<pos, 256>>>(td);
    tohalf_kernel<<<(BM2*DCc + 255)/256, 256>>>(ctx, ctxh, (long long)BM2*DCc);

    // ================= block 1: self-attention =================
    ln_kernel<<<BN, 256>>>(x, ln1_g, ln1_b, lnh);

    mma_gemm<0,2,64><<<ggrid(BN, 3*Ii, 1), 256, SMEM_BK64>>>(lnh, nullptr, wqkv1, nullptr, nullptr,
        v, qh, kh, BN, 3*Ii, Dm, Dm, Dm, Ii, 0,0,0,0,0,0, 1, SCALE);

    head_t64_kernel<<<dim3(Ntok/64, 1, BHh), 256>>>(v, vth, Ntok, Ntok);

    flash_attn<<<dim3(Ntok/128, BHh), 256, FA_SMEM_BYTES>>>(qh, kh, vth, atth);

    mma_gemm<0,0,64><<<ggrid(BN, Dm, 1), 256, SMEM_BK64>>>(atth, nullptr, wo1h, bo1, x,
        x1, nullptr, nullptr, BN, Dm, Ii, Ii, Ii, Dm, 0,0,0,0,0,0, 1, 1.f);

    // ================= block 2: cross-attention =================
    ln_kernel<<<BN, 256>>>(x1, ln2_g, ln2_b, lnh);

    mma_gemm<0,0,64><<<ggrid(BN, Ii, 1), 256, SMEM_BK64>>>(lnh, nullptr, wq2h, nullptr, nullptr,
        nullptr, qh, nullptr, BN, Ii, Dm, Dm, Dm, Ii, 0,0,0,0,0,0, 1, SCALE);

    mma_gemm<0,3,64><<<ggrid(BM2, 2*Ii, 1), 256, SMEM_BK64>>>(ctxh, nullptr, wkv2, nullptr, nullptr,
        v, kh, nullptr, BM2, 2*Ii, DCc, DCc, DCc, Ii, 0,0,0,0,0,0, 1, 1.f);

    head_t64_kernel<<<dim3((MctxP+63)/64, 1, BHh), 256>>>(v, vth, Mctx, MctxP);

    mma_gemm<0,0,64><<<ggrid(Ntok, Mctx, BHh), 256, SMEM_BK64>>>(qh, nullptr, kh, nullptr, nullptr,
        sim, nullptr, nullptr, Ntok, Mctx, DHd, Ii, Ii, MctxP,
        (long long)Ntok*Ii, 64, (long long)Mctx*Ii, 64,
        (long long)Hh*Ntok*MctxP, (long long)Ntok*MctxP, Hh, 1.f);

    softmax_split_kernel<<<BHh*Ntok, 256>>>(sim, Ph, Pl, Mctx, MctxP, MctxP);

    mma_gemm<1,0,32><<<ggrid(Ntok, DHd, BHh), 256, SMEM_BK32S>>>(Ph, Pl, vth, nullptr, nullptr,
        nullptr, atth, nullptr, Ntok, DHd, MctxP, MctxP, MctxP, Ii,
        (long long)Hh*Ntok*MctxP, (long long)Ntok*MctxP,
        (long long)Hh*DHd*MctxP, (long long)DHd*MctxP,
        (long long)Ntok*Ii, 64, Hh, 1.f);

    mma_gemm<0,0,64><<<ggrid(BN, Dm, 1), 256, SMEM_BK64>>>(atth, nullptr, wo2h, bo2, x1,
        x2, nullptr, nullptr, BN, Dm, Ii, Ii, Ii, Dm, 0,0,0,0,0,0, 1, 1.f);

    // ================= block 3: GEGLU FF =================
    ln_kernel<<<BN, 256>>>(x2, ln3_g, ln3_b, lnh);

    mma_gemm<0,1,64><<<ggrid(BN, 2*FFd, 1), 256, SMEM_BK64>>>(lnh, nullptr, wf1h, bff1, nullptr,
        nullptr, ffh, nullptr, BN, 2*FFd, Dm, Dm, Dm, FFd, 0,0,0,0,0,0, 1, 1.f);

    mma_gemm<0,0,64><<<ggrid(BN, Dm, 1), 256, SMEM_BK64>>>(ffh, nullptr, wf2h, bff2, x2,
        out, nullptr, nullptr, BN, Dm, FFd, FFd, FFd, Dm, 0,0,0,0,0,0, 1, 1.f);
}